// round 1
// baseline (speedup 1.0000x reference)
#include <cuda_runtime.h>
#include <math.h>

#define BB 4
#define SS 4096
#define DD 1024
#define FF 4096
#define GG 32
#define BSZ (BB*SS)          // 16384 tokens
#define NC 64                // chunks per sequence
#define CL (SS/NC)           // 64 steps per chunk
static __device__ __constant__ float EPSV = 1e-6f;

// ---------------- scratch (device globals; no allocation allowed) ----------
__device__ float g_q [BSZ*DD];
__device__ float g_kv[BSZ*DD];     // holds k after GEMM, then k*v after prep
__device__ float g_v [BSZ*DD];
__device__ float g_g [BSZ*DD];
__device__ float g_a [BSZ*2*DD];   // [row, 0:D]=a_real->ac_r, [row, D:2D]=a_imag->ac_i
__device__ float g_yr[BSZ*DD];
__device__ float g_yi[BSZ*DD];
__device__ float g_z [BSZ*DD];
__device__ float g_t1[BSZ*DD];
__device__ float g_x1[BSZ*DD];
__device__ float g_h [BSZ*FF];
__device__ float g_Ar[BB*NC*DD], g_Ai[BB*NC*DD], g_Hr[BB*NC*DD], g_Hi[BB*NC*DD];
__device__ float g_Cr[BB*NC*DD], g_Ci[BB*NC*DD];
__device__ float g_gnstat[BB*GG*3];

// ---------------- helpers --------------------------------------------------
__device__ __forceinline__ unsigned f2tf(float x){
    unsigned r; asm("cvt.rna.tf32.f32 %0, %1;" : "=r"(r) : "f"(x)); return r;
}
__device__ __forceinline__ void mma8(float* c,
        unsigned a0,unsigned a1,unsigned a2,unsigned a3,
        unsigned b0,unsigned b1){
    asm volatile(
      "mma.sync.aligned.m16n8k8.row.col.f32.tf32.tf32.f32 "
      "{%0,%1,%2,%3},{%4,%5,%6,%7},{%8,%9},{%0,%1,%2,%3};\n"
      : "+f"(c[0]),"+f"(c[1]),"+f"(c[2]),"+f"(c[3])
      : "r"(a0),"r"(a1),"r"(a2),"r"(a3),"r"(b0),"r"(b1));
}
__device__ __forceinline__ float gelu_f(float x){
    float x3 = x*x*x;
    return 0.5f*x*(1.0f + tanhf(0.7978845608028654f*(x + 0.044715f*x3)));
}
__device__ __forceinline__ float blockSum256(float v){
    __shared__ float sh[8];
    __shared__ float tot;
    #pragma unroll
    for (int off=16; off>0; off>>=1) v += __shfl_down_sync(0xffffffffu, v, off);
    if ((threadIdx.x & 31) == 0) sh[threadIdx.x>>5] = v;
    __syncthreads();
    if (threadIdx.x == 0){
        float t = 0.f;
        #pragma unroll
        for (int i=0;i<8;i++) t += sh[i];
        tot = t;
    }
    __syncthreads();
    float r = tot;
    __syncthreads();   // make repeated calls safe
    return r;
}

// ---------------- 3xTF32 GEMM ---------------------------------------------
// C[M,N] = A[M,K] @ B[K,N] (+bias[N]) (gelu) (+resid[M,N])
// A,B row-major fp32. M%128==0, N%128==0, K%32==0.
template<int ACT>
__global__ void __launch_bounds__(256)
gemm3x(const float* __restrict__ A, const float* __restrict__ Bm,
       float* __restrict__ C, int M, int N, int K,
       const float* __restrict__ bias, const float* __restrict__ resid)
{
    __shared__ float As[128][36];   // +4 pad: conflict-free A frag loads
    __shared__ float Bs[32][136];   // +8 pad: conflict-free B frag loads

    const int tid  = threadIdx.x;
    const int warp = tid >> 5, lane = tid & 31;
    const int grp  = lane >> 2, tq  = lane & 3;
    const int wm   = warp & 3;      // 4 warps along M, 32 rows each
    const int wn   = warp >> 2;     // 2 warps along N, 64 cols each
    const int m0   = blockIdx.y * 128, n0 = blockIdx.x * 128;

    float acc[2][8][4];
    #pragma unroll
    for (int i=0;i<2;i++)
      #pragma unroll
      for (int j=0;j<8;j++)
        #pragma unroll
        for (int r=0;r<4;r++) acc[i][j][r] = 0.f;

    for (int k0 = 0; k0 < K; k0 += 32){
        // global -> shared (raw fp32; hi/lo split happens at fragment load)
        #pragma unroll
        for (int i=0;i<4;i++){
            int lin = tid + 256*i;
            int r = lin >> 3, c4 = lin & 7;
            float4 va = *reinterpret_cast<const float4*>(A + (size_t)(m0+r)*K + k0 + c4*4);
            *reinterpret_cast<float4*>(&As[r][c4*4]) = va;
        }
        #pragma unroll
        for (int i=0;i<4;i++){
            int lin = tid + 256*i;
            int r = lin >> 5, c4 = lin & 31;
            float4 vb = *reinterpret_cast<const float4*>(Bm + (size_t)(k0+r)*N + n0 + c4*4);
            *reinterpret_cast<float4*>(&Bs[r][c4*4]) = vb;
        }
        __syncthreads();

        #pragma unroll
        for (int ks=0; ks<4; ks++){
            const int kk = ks*8;
            unsigned ah[2][4], al[2][4];
            #pragma unroll
            for (int mt=0; mt<2; mt++){
                int r0 = wm*32 + mt*16 + grp;
                float f0 = As[r0  ][kk+tq  ];
                float f1 = As[r0+8][kk+tq  ];
                float f2 = As[r0  ][kk+tq+4];
                float f3 = As[r0+8][kk+tq+4];
                ah[mt][0]=f2tf(f0); al[mt][0]=f2tf(f0-__uint_as_float(ah[mt][0]));
                ah[mt][1]=f2tf(f1); al[mt][1]=f2tf(f1-__uint_as_float(ah[mt][1]));
                ah[mt][2]=f2tf(f2); al[mt][2]=f2tf(f2-__uint_as_float(ah[mt][2]));
                ah[mt][3]=f2tf(f3); al[mt][3]=f2tf(f3-__uint_as_float(ah[mt][3]));
            }
            unsigned bh[8][2], bl[8][2];
            #pragma unroll
            for (int nt=0; nt<8; nt++){
                int c = wn*64 + nt*8 + grp;
                float f0 = Bs[kk+tq  ][c];
                float f1 = Bs[kk+tq+4][c];
                bh[nt][0]=f2tf(f0); bl[nt][0]=f2tf(f0-__uint_as_float(bh[nt][0]));
                bh[nt][1]=f2tf(f1); bl[nt][1]=f2tf(f1-__uint_as_float(bh[nt][1]));
            }
            #pragma unroll
            for (int mt=0; mt<2; mt++)
              #pragma unroll
              for (int nt=0; nt<8; nt++){
                  mma8(acc[mt][nt], ah[mt][0],ah[mt][1],ah[mt][2],ah[mt][3], bh[nt][0],bh[nt][1]);
                  mma8(acc[mt][nt], ah[mt][0],ah[mt][1],ah[mt][2],ah[mt][3], bl[nt][0],bl[nt][1]);
                  mma8(acc[mt][nt], al[mt][0],al[mt][1],al[mt][2],al[mt][3], bh[nt][0],bh[nt][1]);
              }
        }
        __syncthreads();
    }

    // epilogue
    #pragma unroll
    for (int mt=0; mt<2; mt++)
      #pragma unroll
      for (int nt=0; nt<8; nt++){
          int row = m0 + wm*32 + mt*16 + grp;
          int col = n0 + wn*64 + nt*8 + tq*2;
          #pragma unroll
          for (int h=0; h<2; h++){
              int r = row + h*8;
              float v0 = acc[mt][nt][h*2+0];
              float v1 = acc[mt][nt][h*2+1];
              if (bias){ v0 += bias[col]; v1 += bias[col+1]; }
              if (ACT == 1){ v0 = gelu_f(v0); v1 = gelu_f(v1); }
              if (resid){
                  size_t o = (size_t)r*N + col;
                  v0 += resid[o]; v1 += resid[o+1];
              }
              float2 w; w.x = v0; w.y = v1;
              *reinterpret_cast<float2*>(C + (size_t)r*N + col) = w;
          }
      }
}

// ---------------- elementwise prep: a -> sigmoid(|a|)e^{i phase}, kv=k*v ---
__global__ void prep_kernel(){
    int i = blockIdx.x*256 + threadIdx.x;     // < BSZ*DD
    int row = i / DD, d = i % DD;
    size_t abase = (size_t)row*2*DD;
    float ar = g_a[abase + d], ai = g_a[abase + DD + d];
    float mag = sqrtf(ar*ar + ai*ai);
    float sig = 1.f/(1.f + expf(-mag));
    float acr, aci;
    if (mag > 1e-30f){ float s = sig/mag; acr = ar*s; aci = ai*s; }
    else             { acr = sig; aci = 0.f; }
    g_a[abase + d] = acr;
    g_a[abase + DD + d] = aci;
    g_kv[i] = g_kv[i] * g_v[i];
}

// ---------------- 3-phase chunked complex scan -----------------------------
// h_t = a_t*h_{t-1} + kv_t  (a complex, kv real);  y_t = q_t*h_t (q real)
__global__ void scan1(){
    int t = blockIdx.x*256 + threadIdx.x;     // BB*DD*NC threads
    int d = t % DD;
    int t2 = t / DD;
    int chunk = t2 % NC;
    int b = t2 / NC;
    float Ar=1.f, Ai=0.f, Hr=0.f, Hi=0.f;
    size_t srow = (size_t)(b*SS + chunk*CL);
    for (int u=0; u<CL; u++){
        size_t row = srow + u;
        float ar = g_a[row*2*DD + d], ai = g_a[row*2*DD + DD + d];
        float kv = g_kv[row*DD + d];
        float nAr = ar*Ar - ai*Ai,      nAi = ar*Ai + ai*Ar;
        float nHr = ar*Hr - ai*Hi + kv, nHi = ar*Hi + ai*Hr;
        Ar=nAr; Ai=nAi; Hr=nHr; Hi=nHi;
    }
    size_t o = (size_t)(b*NC + chunk)*DD + d;
    g_Ar[o]=Ar; g_Ai[o]=Ai; g_Hr[o]=Hr; g_Hi[o]=Hi;
}
__global__ void scan2(){
    int t = blockIdx.x*256 + threadIdx.x;     // BB*DD threads
    if (t >= BB*DD) return;
    int d = t % DD, b = t / DD;
    float cr=0.f, ci=0.f;
    for (int c=0; c<NC; c++){
        size_t o = (size_t)(b*NC + c)*DD + d;
        g_Cr[o]=cr; g_Ci[o]=ci;
        float Ar=g_Ar[o], Ai=g_Ai[o], Hr=g_Hr[o], Hi=g_Hi[o];
        float nr = Ar*cr - Ai*ci + Hr;
        float ni = Ar*ci + Ai*cr + Hi;
        cr=nr; ci=ni;
    }
}
__global__ void scan3(){
    int t = blockIdx.x*256 + threadIdx.x;
    int d = t % DD;
    int t2 = t / DD;
    int chunk = t2 % NC;
    int b = t2 / NC;
    size_t o = (size_t)(b*NC + chunk)*DD + d;
    float hr = g_Cr[o], hi = g_Ci[o];
    size_t srow = (size_t)(b*SS + chunk*CL);
    for (int u=0; u<CL; u++){
        size_t row = srow + u;
        float ar = g_a[row*2*DD + d], ai = g_a[row*2*DD + DD + d];
        float kv = g_kv[row*DD + d];
        float nhr = ar*hr - ai*hi + kv;
        float nhi = ar*hi + ai*hr;
        hr=nhr; hi=nhi;
        float q = g_q[row*DD + d];
        g_yr[row*DD + d] = q*hr;
        g_yi[row*DD + d] = q*hi;
    }
}

// ---------------- complex GroupNorm stats + gated apply --------------------
__global__ void gnstats(){
    int gi = blockIdx.x;                      // b*GG + g
    int b = gi / GG, g = gi % GG;
    const int DG = DD/GG;                     // 32
    float sr=0.f, si=0.f, s2=0.f;
    for (int idx = threadIdx.x; idx < SS*DG; idx += blockDim.x){
        int s = idx / DG, dc = idx % DG;
        size_t o = ((size_t)(b*SS + s))*DD + g*DG + dc;
        float yr = g_yr[o], yi = g_yi[o];
        sr += yr; si += yi; s2 += yr*yr + yi*yi;
    }
    sr = blockSum256(sr);
    si = blockSum256(si);
    s2 = blockSum256(s2);
    if (threadIdx.x == 0){
        const float cnt = (float)(SS*DG);
        float mr = sr/cnt, mi = si/cnt;
        float var = s2/cnt - mr*mr - mi*mi;
        g_gnstat[gi*3+0] = mr;
        g_gnstat[gi*3+1] = mi;
        g_gnstat[gi*3+2] = rsqrtf(var + EPSV);
    }
}
__global__ void gapply(const float* __restrict__ gn_scale,
                       const float* __restrict__ gn_bias){
    int i = blockIdx.x*256 + threadIdx.x;
    int row = i / DD, d = i % DD;
    int b = row / SS;
    int gi = b*GG + d/(DD/GG);
    float mr  = g_gnstat[gi*3+0];
    float inv = g_gnstat[gi*3+2];
    // only the real part survives (Wo real, silu(g) real)
    float yn = (g_yr[i] - mr)*inv*gn_scale[d] + gn_bias[d];
    float gv = g_g[i];
    float silu = gv / (1.f + expf(-gv));
    g_z[i] = yn * silu;
}

// ---------------- rowwise LayerNorm (optional residual add) ----------------
__global__ void ln_kernel(const float* __restrict__ xin,
                          const float* __restrict__ addin,
                          float* __restrict__ out,
                          const float* __restrict__ sc,
                          const float* __restrict__ bi){
    int row = blockIdx.x;
    int tid = threadIdx.x;                    // 256 threads, 4 elems each
    size_t base = (size_t)row*DD + tid*4;
    float4 v = *reinterpret_cast<const float4*>(xin + base);
    if (addin){
        float4 w = *reinterpret_cast<const float4*>(addin + base);
        v.x += w.x; v.y += w.y; v.z += w.z; v.w += w.w;
    }
    float s = v.x + v.y + v.z + v.w;
    float mu = blockSum256(s) * (1.f/DD);
    float dx = v.x-mu, dy = v.y-mu, dz = v.z-mu, dw = v.w-mu;
    float sq = dx*dx + dy*dy + dz*dz + dw*dw;
    float var = blockSum256(sq) * (1.f/DD);
    float inv = rsqrtf(var + EPSV);
    int c = tid*4;
    float4 o;
    o.x = dx*inv*sc[c+0] + bi[c+0];
    o.y = dy*inv*sc[c+1] + bi[c+1];
    o.z = dz*inv*sc[c+2] + bi[c+2];
    o.w = dw*inv*sc[c+3] + bi[c+3];
    *reinterpret_cast<float4*>(out + base) = o;
}

// ---------------- launch ---------------------------------------------------
extern "C" void kernel_launch(void* const* d_in, const int* in_sizes, int n_in,
                              void* d_out, int out_size){
    const float* x         = (const float*)d_in[0];
    const float* Wq        = (const float*)d_in[1];
    const float* Wk        = (const float*)d_in[2];
    const float* Wv        = (const float*)d_in[3];
    const float* Wa        = (const float*)d_in[4];
    const float* Wg        = (const float*)d_in[5];
    const float* Wo        = (const float*)d_in[6];
    const float* gn_scale  = (const float*)d_in[7];
    const float* gn_bias   = (const float*)d_in[8];
    const float* ln1_scale = (const float*)d_in[9];
    const float* ln1_bias  = (const float*)d_in[10];
    const float* W1        = (const float*)d_in[11];
    const float* b1        = (const float*)d_in[12];
    const float* W2        = (const float*)d_in[13];
    const float* b2        = (const float*)d_in[14];
    const float* ln2_scale = (const float*)d_in[15];
    const float* ln2_bias  = (const float*)d_in[16];
    float* out = (float*)d_out;

    float *pq,*pkv,*pv,*pg,*pa,*pz,*pt1,*px1,*ph;
    cudaGetSymbolAddress((void**)&pq,  g_q);
    cudaGetSymbolAddress((void**)&pkv, g_kv);
    cudaGetSymbolAddress((void**)&pv,  g_v);
    cudaGetSymbolAddress((void**)&pg,  g_g);
    cudaGetSymbolAddress((void**)&pa,  g_a);
    cudaGetSymbolAddress((void**)&pz,  g_z);
    cudaGetSymbolAddress((void**)&pt1, g_t1);
    cudaGetSymbolAddress((void**)&px1, g_x1);
    cudaGetSymbolAddress((void**)&ph,  g_h);

    dim3 blk(256);
    dim3 gD (DD/128,   BSZ/128);   // N=1024
    dim3 gA (2*DD/128, BSZ/128);   // N=2048
    dim3 gF (FF/128,   BSZ/128);   // N=4096

    gemm3x<0><<<gD, blk>>>(x, Wq, pq,  BSZ, DD,   DD, nullptr, nullptr);
    gemm3x<0><<<gD, blk>>>(x, Wk, pkv, BSZ, DD,   DD, nullptr, nullptr);
    gemm3x<0><<<gD, blk>>>(x, Wv, pv,  BSZ, DD,   DD, nullptr, nullptr);
    gemm3x<0><<<gD, blk>>>(x, Wg, pg,  BSZ, DD,   DD, nullptr, nullptr);
    gemm3x<0><<<gA, blk>>>(x, Wa, pa,  BSZ, 2*DD, DD, nullptr, nullptr);

    prep_kernel<<<BSZ*DD/256, 256>>>();
    scan1<<<BB*DD*NC/256, 256>>>();
    scan2<<<(BB*DD+255)/256, 256>>>();
    scan3<<<BB*DD*NC/256, 256>>>();
    gnstats<<<BB*GG, 256>>>();
    gapply<<<BSZ*DD/256, 256>>>(gn_scale, gn_bias);

    gemm3x<0><<<gD, blk>>>(pz, Wo, pt1, BSZ, DD, DD, nullptr, nullptr);
    ln_kernel<<<BSZ, 256>>>(x, pt1, px1, ln1_scale, ln1_bias);

    gemm3x<1><<<gF, blk>>>(px1, W1, ph,  BSZ, FF, DD, b1, nullptr);    // gelu
    gemm3x<0><<<gD, blk>>>(ph,  W2, pt1, BSZ, DD, FF, b2, px1);        // +bias+resid

    ln_kernel<<<BSZ, 256>>>(pt1, nullptr, out, ln2_scale, ln2_bias);
}

// round 2
// speedup vs baseline: 1.6698x; 1.6698x over previous
#include <cuda_runtime.h>
#include <cuda_bf16.h>
#include <math.h>

#define BB 4
#define SS 4096
#define DD 1024
#define FF 4096
#define GG 32
#define BSZ (BB*SS)          // 16384 tokens
#define NC 64                // chunks per sequence
#define CL (SS/NC)           // 64 steps per chunk
#define MEL (1024*1024)
static __device__ __constant__ float EPSV = 1e-6f;

// ---------------- scratch (device globals; no allocation allowed) ----------
__device__ float g_q [BSZ*DD];
__device__ float g_kv[BSZ*DD];
__device__ float g_v [BSZ*DD];
__device__ float g_g [BSZ*DD];
__device__ float g_a [BSZ*2*DD];
__device__ float g_yr[BSZ*DD];
__device__ float g_yi[BSZ*DD];
__device__ float g_z [BSZ*DD];
__device__ float g_t1[BSZ*DD];
__device__ float g_x1[BSZ*DD];
__device__ float g_h [BSZ*FF];
__device__ float g_wt[13*MEL];     // transposed weights [N][K]
__device__ float g_Ar[BB*NC*DD], g_Ai[BB*NC*DD], g_Hr[BB*NC*DD], g_Hi[BB*NC*DD];
__device__ float g_Cr[BB*NC*DD], g_Ci[BB*NC*DD];
__device__ float g_gnstat[BB*GG*3];

// ---------------- helpers --------------------------------------------------
__device__ __forceinline__ unsigned f2tf(float x){
    unsigned r; asm("cvt.rna.tf32.f32 %0, %1;" : "=r"(r) : "f"(x)); return r;
}
__device__ __forceinline__ void mma8(float* c,
        unsigned a0,unsigned a1,unsigned a2,unsigned a3,
        unsigned b0,unsigned b1){
    asm volatile(
      "mma.sync.aligned.m16n8k8.row.col.f32.tf32.tf32.f32 "
      "{%0,%1,%2,%3},{%4,%5,%6,%7},{%8,%9},{%0,%1,%2,%3};\n"
      : "+f"(c[0]),"+f"(c[1]),"+f"(c[2]),"+f"(c[3])
      : "r"(a0),"r"(a1),"r"(a2),"r"(a3),"r"(b0),"r"(b1));
}
__device__ __forceinline__ void mma16(float* c,
        unsigned a0,unsigned a1,unsigned a2,unsigned a3,
        unsigned b0,unsigned b1){
    asm volatile(
      "mma.sync.aligned.m16n8k16.row.col.f32.bf16.bf16.f32 "
      "{%0,%1,%2,%3},{%4,%5,%6,%7},{%8,%9},{%0,%1,%2,%3};\n"
      : "+f"(c[0]),"+f"(c[1]),"+f"(c[2]),"+f"(c[3])
      : "r"(a0),"r"(a1),"r"(a2),"r"(a3),"r"(b0),"r"(b1));
}
__device__ __forceinline__ float gelu_f(float x){
    float x3 = x*x*x;
    return 0.5f*x*(1.0f + tanhf(0.7978845608028654f*(x + 0.044715f*x3)));
}
__device__ __forceinline__ void split2(float x0, float x1, unsigned &h, unsigned &l){
    __nv_bfloat16 h0 = __float2bfloat16(x0), h1 = __float2bfloat16(x1);
    float r0 = x0 - __bfloat162float(h0);
    float r1 = x1 - __bfloat162float(h1);
    __nv_bfloat16 l0 = __float2bfloat16(r0), l1 = __float2bfloat16(r1);
    h = ((unsigned)__bfloat16_as_ushort(h1) << 16) | (unsigned)__bfloat16_as_ushort(h0);
    l = ((unsigned)__bfloat16_as_ushort(l1) << 16) | (unsigned)__bfloat16_as_ushort(l0);
}
__device__ __forceinline__ float blockSum256(float v){
    __shared__ float sh[8];
    __shared__ float tot;
    #pragma unroll
    for (int off=16; off>0; off>>=1) v += __shfl_down_sync(0xffffffffu, v, off);
    if ((threadIdx.x & 31) == 0) sh[threadIdx.x>>5] = v;
    __syncthreads();
    if (threadIdx.x == 0){
        float t = 0.f;
        #pragma unroll
        for (int i=0;i<8;i++) t += sh[i];
        tot = t;
    }
    __syncthreads();
    float r = tot;
    __syncthreads();
    return r;
}

// ---------------- weight transpose: in[R][C] -> out[C][R] -------------------
__global__ void tpose(const float* __restrict__ in, float* __restrict__ out,
                      int R, int C){
    __shared__ float t[32][33];
    int bx = blockIdx.x*32, by = blockIdx.y*32;
    int x = bx + threadIdx.x;
    #pragma unroll
    for (int j=0;j<4;j++){
        int y = by + threadIdx.y + j*8;
        t[threadIdx.y + j*8][threadIdx.x] = in[(size_t)y*C + x];
    }
    __syncthreads();
    int xo = by + threadIdx.x;
    #pragma unroll
    for (int j=0;j<4;j++){
        int yo = bx + threadIdx.y + j*8;
        out[(size_t)yo*R + xo] = t[threadIdx.x][threadIdx.y + j*8];
    }
}

// ---------------- 3xBF16 GEMM (B pre-transposed to [N][K]) ------------------
// C[M,N] = A[M,K] @ B[K,N] with Bt[n][k] = B[k][n].
// 128x128 block tile, k-step 32, double-buffered via registers.
#define PLN (128*40)
template<int ACT>
__global__ void __launch_bounds__(256)
gemm_bf3(const float* __restrict__ A, const float* __restrict__ Bt,
         float* __restrict__ C, int M, int N, int K,
         const float* __restrict__ bias, const float* __restrict__ resid)
{
    extern __shared__ __nv_bfloat16 dsm[];   // 8 planes of 128x40 bf16

    const int tid  = threadIdx.x;
    const int warp = tid >> 5, lane = tid & 31;
    const int grp  = lane >> 2, tq  = lane & 3;
    const int wm   = warp & 3;      // 4 warps along M (32 rows each)
    const int wn   = warp >> 2;     // 2 warps along N (64 cols each)
    const int m0   = blockIdx.y * 128, n0 = blockIdx.x * 128;
    const int lr   = tid >> 3;      // load row 0..127
    const int lc4  = tid & 7;       // load col group (float4)

    float acc[2][8][4];
    #pragma unroll
    for (int i=0;i<2;i++)
      #pragma unroll
      for (int j=0;j<8;j++)
        #pragma unroll
        for (int r=0;r<4;r++) acc[i][j][r] = 0.f;

    float4 ra[4], rb[4];
    const float* Arow = A  + (size_t)(m0 + lr)*K + lc4*4;
    const float* Brow = Bt + (size_t)(n0 + lr)*K + lc4*4;

    // prologue: load tile 0
    #pragma unroll
    for (int i=0;i<4;i++){
        ra[i] = *reinterpret_cast<const float4*>(Arow + (size_t)(i*32)*K);
        rb[i] = *reinterpret_cast<const float4*>(Brow + (size_t)(i*32)*K);
    }
    {   // cvt + store to buffer 0
        __nv_bfloat16* Ah = dsm + 0*PLN; __nv_bfloat16* Al = dsm + 1*PLN;
        __nv_bfloat16* Bh = dsm + 2*PLN; __nv_bfloat16* Bl = dsm + 3*PLN;
        #pragma unroll
        for (int i=0;i<4;i++){
            int off = (lr + i*32)*40 + lc4*4;
            unsigned h0,l0,h1,l1;
            split2(ra[i].x, ra[i].y, h0, l0);
            split2(ra[i].z, ra[i].w, h1, l1);
            *reinterpret_cast<uint2*>(Ah+off) = make_uint2(h0,h1);
            *reinterpret_cast<uint2*>(Al+off) = make_uint2(l0,l1);
            split2(rb[i].x, rb[i].y, h0, l0);
            split2(rb[i].z, rb[i].w, h1, l1);
            *reinterpret_cast<uint2*>(Bh+off) = make_uint2(h0,h1);
            *reinterpret_cast<uint2*>(Bl+off) = make_uint2(l0,l1);
        }
    }
    __syncthreads();

    const int nIter = K >> 5;
    for (int it = 0; it < nIter; it++){
        int buf = it & 1;
        const __nv_bfloat16* Ah = dsm + (buf*4+0)*PLN;
        const __nv_bfloat16* Al = dsm + (buf*4+1)*PLN;
        const __nv_bfloat16* Bh = dsm + (buf*4+2)*PLN;
        const __nv_bfloat16* Bl = dsm + (buf*4+3)*PLN;

        // issue next tile's global loads (hidden behind compute)
        bool more = (it+1 < nIter);
        if (more){
            const float* An = Arow + (size_t)(it+1)*32;
            const float* Bn = Brow + (size_t)(it+1)*32;
            #pragma unroll
            for (int i=0;i<4;i++){
                ra[i] = *reinterpret_cast<const float4*>(An + (size_t)(i*32)*K);
                rb[i] = *reinterpret_cast<const float4*>(Bn + (size_t)(i*32)*K);
            }
        }

        #pragma unroll
        for (int ks=0; ks<2; ks++){
            const int kk = ks*16 + tq*2;
            unsigned ah[2][4], al2[2][4];
            #pragma unroll
            for (int mt=0; mt<2; mt++){
                int r0 = wm*32 + mt*16 + grp;
                ah[mt][0]  = *reinterpret_cast<const unsigned*>(Ah + r0*40     + kk);
                ah[mt][1]  = *reinterpret_cast<const unsigned*>(Ah + (r0+8)*40 + kk);
                ah[mt][2]  = *reinterpret_cast<const unsigned*>(Ah + r0*40     + kk+8);
                ah[mt][3]  = *reinterpret_cast<const unsigned*>(Ah + (r0+8)*40 + kk+8);
                al2[mt][0] = *reinterpret_cast<const unsigned*>(Al + r0*40     + kk);
                al2[mt][1] = *reinterpret_cast<const unsigned*>(Al + (r0+8)*40 + kk);
                al2[mt][2] = *reinterpret_cast<const unsigned*>(Al + r0*40     + kk+8);
                al2[mt][3] = *reinterpret_cast<const unsigned*>(Al + (r0+8)*40 + kk+8);
            }
            unsigned bh2[8][2], bl2[8][2];
            #pragma unroll
            for (int nt=0; nt<8; nt++){
                int c = wn*64 + nt*8 + grp;
                bh2[nt][0] = *reinterpret_cast<const unsigned*>(Bh + c*40 + kk);
                bh2[nt][1] = *reinterpret_cast<const unsigned*>(Bh + c*40 + kk+8);
                bl2[nt][0] = *reinterpret_cast<const unsigned*>(Bl + c*40 + kk);
                bl2[nt][1] = *reinterpret_cast<const unsigned*>(Bl + c*40 + kk+8);
            }
            #pragma unroll
            for (int mt=0; mt<2; mt++)
              #pragma unroll
              for (int nt=0; nt<8; nt++){
                  mma16(acc[mt][nt], ah[mt][0],ah[mt][1],ah[mt][2],ah[mt][3],
                                     bh2[nt][0],bh2[nt][1]);
                  mma16(acc[mt][nt], ah[mt][0],ah[mt][1],ah[mt][2],ah[mt][3],
                                     bl2[nt][0],bl2[nt][1]);
                  mma16(acc[mt][nt], al2[mt][0],al2[mt][1],al2[mt][2],al2[mt][3],
                                     bh2[nt][0],bh2[nt][1]);
              }
        }

        if (more){
            int nb = (it+1) & 1;
            __nv_bfloat16* nAh = dsm + (nb*4+0)*PLN; __nv_bfloat16* nAl = dsm + (nb*4+1)*PLN;
            __nv_bfloat16* nBh = dsm + (nb*4+2)*PLN; __nv_bfloat16* nBl = dsm + (nb*4+3)*PLN;
            #pragma unroll
            for (int i=0;i<4;i++){
                int off = (lr + i*32)*40 + lc4*4;
                unsigned h0,l0,h1,l1;
                split2(ra[i].x, ra[i].y, h0, l0);
                split2(ra[i].z, ra[i].w, h1, l1);
                *reinterpret_cast<uint2*>(nAh+off) = make_uint2(h0,h1);
                *reinterpret_cast<uint2*>(nAl+off) = make_uint2(l0,l1);
                split2(rb[i].x, rb[i].y, h0, l0);
                split2(rb[i].z, rb[i].w, h1, l1);
                *reinterpret_cast<uint2*>(nBh+off) = make_uint2(h0,h1);
                *reinterpret_cast<uint2*>(nBl+off) = make_uint2(l0,l1);
            }
            __syncthreads();
        }
    }

    // epilogue
    #pragma unroll
    for (int mt=0; mt<2; mt++)
      #pragma unroll
      for (int nt=0; nt<8; nt++){
          int row = m0 + wm*32 + mt*16 + grp;
          int col = n0 + wn*64 + nt*8 + tq*2;
          #pragma unroll
          for (int h=0; h<2; h++){
              int r = row + h*8;
              float v0 = acc[mt][nt][h*2+0];
              float v1 = acc[mt][nt][h*2+1];
              if (bias){ v0 += bias[col]; v1 += bias[col+1]; }
              if (ACT == 1){ v0 = gelu_f(v0); v1 = gelu_f(v1); }
              if (resid){
                  size_t o = (size_t)r*N + col;
                  v0 += resid[o]; v1 += resid[o+1];
              }
              float2 w; w.x = v0; w.y = v1;
              *reinterpret_cast<float2*>(C + (size_t)r*N + col) = w;
          }
      }
}

// ---------------- 3xTF32 GEMM (kept for the precision-critical Wa) ---------
template<int ACT>
__global__ void __launch_bounds__(256)
gemm3x(const float* __restrict__ A, const float* __restrict__ Bm,
       float* __restrict__ C, int M, int N, int K,
       const float* __restrict__ bias, const float* __restrict__ resid)
{
    __shared__ float As[128][36];
    __shared__ float Bs[32][136];

    const int tid  = threadIdx.x;
    const int warp = tid >> 5, lane = tid & 31;
    const int grp  = lane >> 2, tq  = lane & 3;
    const int wm   = warp & 3;
    const int wn   = warp >> 2;
    const int m0   = blockIdx.y * 128, n0 = blockIdx.x * 128;

    float acc[2][8][4];
    #pragma unroll
    for (int i=0;i<2;i++)
      #pragma unroll
      for (int j=0;j<8;j++)
        #pragma unroll
        for (int r=0;r<4;r++) acc[i][j][r] = 0.f;

    for (int k0 = 0; k0 < K; k0 += 32){
        #pragma unroll
        for (int i=0;i<4;i++){
            int lin = tid + 256*i;
            int r = lin >> 3, c4 = lin & 7;
            float4 va = *reinterpret_cast<const float4*>(A + (size_t)(m0+r)*K + k0 + c4*4);
            *reinterpret_cast<float4*>(&As[r][c4*4]) = va;
        }
        #pragma unroll
        for (int i=0;i<4;i++){
            int lin = tid + 256*i;
            int r = lin >> 5, c4 = lin & 31;
            float4 vb = *reinterpret_cast<const float4*>(Bm + (size_t)(k0+r)*N + n0 + c4*4);
            *reinterpret_cast<float4*>(&Bs[r][c4*4]) = vb;
        }
        __syncthreads();

        #pragma unroll
        for (int ks=0; ks<4; ks++){
            const int kk = ks*8;
            unsigned ah[2][4], al[2][4];
            #pragma unroll
            for (int mt=0; mt<2; mt++){
                int r0 = wm*32 + mt*16 + grp;
                float f0 = As[r0  ][kk+tq  ];
                float f1 = As[r0+8][kk+tq  ];
                float f2 = As[r0  ][kk+tq+4];
                float f3 = As[r0+8][kk+tq+4];
                ah[mt][0]=f2tf(f0); al[mt][0]=f2tf(f0-__uint_as_float(ah[mt][0]));
                ah[mt][1]=f2tf(f1); al[mt][1]=f2tf(f1-__uint_as_float(ah[mt][1]));
                ah[mt][2]=f2tf(f2); al[mt][2]=f2tf(f2-__uint_as_float(ah[mt][2]));
                ah[mt][3]=f2tf(f3); al[mt][3]=f2tf(f3-__uint_as_float(ah[mt][3]));
            }
            unsigned bh[8][2], bl[8][2];
            #pragma unroll
            for (int nt=0; nt<8; nt++){
                int c = wn*64 + nt*8 + grp;
                float f0 = Bs[kk+tq  ][c];
                float f1 = Bs[kk+tq+4][c];
                bh[nt][0]=f2tf(f0); bl[nt][0]=f2tf(f0-__uint_as_float(bh[nt][0]));
                bh[nt][1]=f2tf(f1); bl[nt][1]=f2tf(f1-__uint_as_float(bh[nt][1]));
            }
            #pragma unroll
            for (int mt=0; mt<2; mt++)
              #pragma unroll
              for (int nt=0; nt<8; nt++){
                  mma8(acc[mt][nt], ah[mt][0],ah[mt][1],ah[mt][2],ah[mt][3], bh[nt][0],bh[nt][1]);
                  mma8(acc[mt][nt], ah[mt][0],ah[mt][1],ah[mt][2],ah[mt][3], bl[nt][0],bl[nt][1]);
                  mma8(acc[mt][nt], al[mt][0],al[mt][1],al[mt][2],al[mt][3], bh[nt][0],bh[nt][1]);
              }
        }
        __syncthreads();
    }

    #pragma unroll
    for (int mt=0; mt<2; mt++)
      #pragma unroll
      for (int nt=0; nt<8; nt++){
          int row = m0 + wm*32 + mt*16 + grp;
          int col = n0 + wn*64 + nt*8 + tq*2;
          #pragma unroll
          for (int h=0; h<2; h++){
              int r = row + h*8;
              float v0 = acc[mt][nt][h*2+0];
              float v1 = acc[mt][nt][h*2+1];
              if (bias){ v0 += bias[col]; v1 += bias[col+1]; }
              if (ACT == 1){ v0 = gelu_f(v0); v1 = gelu_f(v1); }
              if (resid){
                  size_t o = (size_t)r*N + col;
                  v0 += resid[o]; v1 += resid[o+1];
              }
              float2 w; w.x = v0; w.y = v1;
              *reinterpret_cast<float2*>(C + (size_t)r*N + col) = w;
          }
      }
}

// ---------------- elementwise prep ------------------------------------------
__global__ void prep_kernel(){
    int i = blockIdx.x*256 + threadIdx.x;
    int row = i / DD, d = i % DD;
    size_t abase = (size_t)row*2*DD;
    float ar = g_a[abase + d], ai = g_a[abase + DD + d];
    float mag = sqrtf(ar*ar + ai*ai);
    float sig = 1.f/(1.f + expf(-mag));
    float acr, aci;
    if (mag > 1e-30f){ float s = sig/mag; acr = ar*s; aci = ai*s; }
    else             { acr = sig; aci = 0.f; }
    g_a[abase + d] = acr;
    g_a[abase + DD + d] = aci;
    g_kv[i] = g_kv[i] * g_v[i];
}

// ---------------- 3-phase chunked complex scan -------------------------------
__global__ void scan1(){
    int t = blockIdx.x*256 + threadIdx.x;
    int d = t % DD;
    int t2 = t / DD;
    int chunk = t2 % NC;
    int b = t2 / NC;
    float Ar=1.f, Ai=0.f, Hr=0.f, Hi=0.f;
    size_t srow = (size_t)(b*SS + chunk*CL);
    for (int u=0; u<CL; u++){
        size_t row = srow + u;
        float ar = g_a[row*2*DD + d], ai = g_a[row*2*DD + DD + d];
        float kv = g_kv[row*DD + d];
        float nAr = ar*Ar - ai*Ai,      nAi = ar*Ai + ai*Ar;
        float nHr = ar*Hr - ai*Hi + kv, nHi = ar*Hi + ai*Hr;
        Ar=nAr; Ai=nAi; Hr=nHr; Hi=nHi;
    }
    size_t o = (size_t)(b*NC + chunk)*DD + d;
    g_Ar[o]=Ar; g_Ai[o]=Ai; g_Hr[o]=Hr; g_Hi[o]=Hi;
}
__global__ void scan2(){
    int t = blockIdx.x*256 + threadIdx.x;
    if (t >= BB*DD) return;
    int d = t % DD, b = t / DD;
    float cr=0.f, ci=0.f;
    for (int c=0; c<NC; c++){
        size_t o = (size_t)(b*NC + c)*DD + d;
        g_Cr[o]=cr; g_Ci[o]=ci;
        float Ar=g_Ar[o], Ai=g_Ai[o], Hr=g_Hr[o], Hi=g_Hi[o];
        float nr = Ar*cr - Ai*ci + Hr;
        float ni = Ar*ci + Ai*cr + Hi;
        cr=nr; ci=ni;
    }
}
__global__ void scan3(){
    int t = blockIdx.x*256 + threadIdx.x;
    int d = t % DD;
    int t2 = t / DD;
    int chunk = t2 % NC;
    int b = t2 / NC;
    size_t o = (size_t)(b*NC + chunk)*DD + d;
    float hr = g_Cr[o], hi = g_Ci[o];
    size_t srow = (size_t)(b*SS + chunk*CL);
    for (int u=0; u<CL; u++){
        size_t row = srow + u;
        float ar = g_a[row*2*DD + d], ai = g_a[row*2*DD + DD + d];
        float kv = g_kv[row*DD + d];
        float nhr = ar*hr - ai*hi + kv;
        float nhi = ar*hi + ai*hr;
        hr=nhr; hi=nhi;
        float q = g_q[row*DD + d];
        g_yr[row*DD + d] = q*hr;
        g_yi[row*DD + d] = q*hi;
    }
}

// ---------------- complex GroupNorm stats + gated apply ----------------------
__global__ void gnstats(){
    int gi = blockIdx.x;
    int b = gi / GG, g = gi % GG;
    const int DG = DD/GG;
    float sr=0.f, si=0.f, s2=0.f;
    for (int idx = threadIdx.x; idx < SS*DG; idx += blockDim.x){
        int s = idx / DG, dc = idx % DG;
        size_t o = ((size_t)(b*SS + s))*DD + g*DG + dc;
        float yr = g_yr[o], yi = g_yi[o];
        sr += yr; si += yi; s2 += yr*yr + yi*yi;
    }
    sr = blockSum256(sr);
    si = blockSum256(si);
    s2 = blockSum256(s2);
    if (threadIdx.x == 0){
        const float cnt = (float)(SS*DG);
        float mr = sr/cnt, mi = si/cnt;
        float var = s2/cnt - mr*mr - mi*mi;
        g_gnstat[gi*3+0] = mr;
        g_gnstat[gi*3+1] = mi;
        g_gnstat[gi*3+2] = rsqrtf(var + EPSV);
    }
}
__global__ void gapply(const float* __restrict__ gn_scale,
                       const float* __restrict__ gn_bias){
    int i = blockIdx.x*256 + threadIdx.x;
    int row = i / DD, d = i % DD;
    int b = row / SS;
    int gi = b*GG + d/(DD/GG);
    float mr  = g_gnstat[gi*3+0];
    float inv = g_gnstat[gi*3+2];
    float yn = (g_yr[i] - mr)*inv*gn_scale[d] + gn_bias[d];
    float gv = g_g[i];
    float silu = gv / (1.f + expf(-gv));
    g_z[i] = yn * silu;
}

// ---------------- rowwise LayerNorm ------------------------------------------
__global__ void ln_kernel(const float* __restrict__ xin,
                          const float* __restrict__ addin,
                          float* __restrict__ out,
                          const float* __restrict__ sc,
                          const float* __restrict__ bi){
    int row = blockIdx.x;
    int tid = threadIdx.x;
    size_t base = (size_t)row*DD + tid*4;
    float4 v = *reinterpret_cast<const float4*>(xin + base);
    if (addin){
        float4 w = *reinterpret_cast<const float4*>(addin + base);
        v.x += w.x; v.y += w.y; v.z += w.z; v.w += w.w;
    }
    float s = v.x + v.y + v.z + v.w;
    float mu = blockSum256(s) * (1.f/DD);
    float dx = v.x-mu, dy = v.y-mu, dz = v.z-mu, dw = v.w-mu;
    float sq = dx*dx + dy*dy + dz*dz + dw*dw;
    float var = blockSum256(sq) * (1.f/DD);
    float inv = rsqrtf(var + EPSV);
    int c = tid*4;
    float4 o;
    o.x = dx*inv*sc[c+0] + bi[c+0];
    o.y = dy*inv*sc[c+1] + bi[c+1];
    o.z = dz*inv*sc[c+2] + bi[c+2];
    o.w = dw*inv*sc[c+3] + bi[c+3];
    *reinterpret_cast<float4*>(out + base) = o;
}

// ---------------- launch ------------------------------------------------------
extern "C" void kernel_launch(void* const* d_in, const int* in_sizes, int n_in,
                              void* d_out, int out_size){
    const float* x         = (const float*)d_in[0];
    const float* Wq        = (const float*)d_in[1];
    const float* Wk        = (const float*)d_in[2];
    const float* Wv        = (const float*)d_in[3];
    const float* Wa        = (const float*)d_in[4];
    const float* Wg        = (const float*)d_in[5];
    const float* Wo        = (const float*)d_in[6];
    const float* gn_scale  = (const float*)d_in[7];
    const float* gn_bias   = (const float*)d_in[8];
    const float* ln1_scale = (const float*)d_in[9];
    const float* ln1_bias  = (const float*)d_in[10];
    const float* W1        = (const float*)d_in[11];
    const float* b1        = (const float*)d_in[12];
    const float* W2        = (const float*)d_in[13];
    const float* b2        = (const float*)d_in[14];
    const float* ln2_scale = (const float*)d_in[15];
    const float* ln2_bias  = (const float*)d_in[16];
    float* out = (float*)d_out;

    float *pq,*pkv,*pv,*pg,*pa,*pz,*pt1,*px1,*ph,*pwt;
    cudaGetSymbolAddress((void**)&pq,  g_q);
    cudaGetSymbolAddress((void**)&pkv, g_kv);
    cudaGetSymbolAddress((void**)&pv,  g_v);
    cudaGetSymbolAddress((void**)&pg,  g_g);
    cudaGetSymbolAddress((void**)&pa,  g_a);
    cudaGetSymbolAddress((void**)&pz,  g_z);
    cudaGetSymbolAddress((void**)&pt1, g_t1);
    cudaGetSymbolAddress((void**)&px1, g_x1);
    cudaGetSymbolAddress((void**)&ph,  g_h);
    cudaGetSymbolAddress((void**)&pwt, g_wt);

    float* wtq = pwt + 0*MEL;
    float* wtk = pwt + 1*MEL;
    float* wtv = pwt + 2*MEL;
    float* wtg = pwt + 3*MEL;
    float* wto = pwt + 4*MEL;
    float* wt1 = pwt + 5*MEL;   // [FF][DD]
    float* wt2 = pwt + 9*MEL;   // [DD][FF]

    static int smem_set = 0;
    const int GEMM_SMEM = 8*PLN*2;   // 81920 bytes
    if (!smem_set){
        cudaFuncSetAttribute(gemm_bf3<0>, cudaFuncAttributeMaxDynamicSharedMemorySize, GEMM_SMEM);
        cudaFuncSetAttribute(gemm_bf3<1>, cudaFuncAttributeMaxDynamicSharedMemorySize, GEMM_SMEM);
        smem_set = 1;
    }

    dim3 tb(32,8);
    tpose<<<dim3(DD/32, DD/32), tb>>>(Wq, wtq, DD, DD);
    tpose<<<dim3(DD/32, DD/32), tb>>>(Wk, wtk, DD, DD);
    tpose<<<dim3(DD/32, DD/32), tb>>>(Wv, wtv, DD, DD);
    tpose<<<dim3(DD/32, DD/32), tb>>>(Wg, wtg, DD, DD);
    tpose<<<dim3(DD/32, DD/32), tb>>>(Wo, wto, DD, DD);
    tpose<<<dim3(FF/32, DD/32), tb>>>(W1, wt1, DD, FF);
    tpose<<<dim3(DD/32, FF/32), tb>>>(W2, wt2, FF, DD);

    dim3 blk(256);
    dim3 gD (DD/128,   BSZ/128);
    dim3 gA (2*DD/128, BSZ/128);
    dim3 gF (FF/128,   BSZ/128);

    gemm_bf3<0><<<gD, blk, GEMM_SMEM>>>(x, wtq, pq,  BSZ, DD, DD, nullptr, nullptr);
    gemm_bf3<0><<<gD, blk, GEMM_SMEM>>>(x, wtk, pkv, BSZ, DD, DD, nullptr, nullptr);
    gemm_bf3<0><<<gD, blk, GEMM_SMEM>>>(x, wtv, pv,  BSZ, DD, DD, nullptr, nullptr);
    gemm_bf3<0><<<gD, blk, GEMM_SMEM>>>(x, wtg, pg,  BSZ, DD, DD, nullptr, nullptr);
    gemm3x<0><<<gA, blk>>>(x, Wa, pa, BSZ, 2*DD, DD, nullptr, nullptr);  // precision-critical

    prep_kernel<<<BSZ*DD/256, 256>>>();
    scan1<<<BB*DD*NC/256, 256>>>();
    scan2<<<(BB*DD+255)/256, 256>>>();
    scan3<<<BB*DD*NC/256, 256>>>();
    gnstats<<<BB*GG, 256>>>();
    gapply<<<BSZ*DD/256, 256>>>(gn_scale, gn_bias);

    gemm_bf3<0><<<gD, blk, GEMM_SMEM>>>(pz, wto, pt1, BSZ, DD, DD, nullptr, nullptr);
    ln_kernel<<<BSZ, 256>>>(x, pt1, px1, ln1_scale, ln1_bias);

    gemm_bf3<1><<<gF, blk, GEMM_SMEM>>>(px1, wt1, ph,  BSZ, FF, DD, b1, nullptr);
    gemm_bf3<0><<<gD, blk, GEMM_SMEM>>>(ph,  wt2, pt1, BSZ, DD, FF, b2, px1);

    ln_kernel<<<BSZ, 256>>>(pt1, nullptr, out, ln2_scale, ln2_bias);
}

// round 3
// speedup vs baseline: 1.7569x; 1.0522x over previous
#include <cuda_runtime.h>
#include <cuda_bf16.h>
#include <math.h>

#define BB 4
#define SS 4096
#define DD 1024
#define FF 4096
#define GG 32
#define BSZ (BB*SS)          // 16384 tokens
#define NC 64                // chunks per sequence
#define CL (SS/NC)           // 64 steps per chunk
#define MEL (1024*1024)
static __device__ __constant__ float EPSV = 1e-6f;

// ---------------- scratch (device globals; no allocation allowed) ----------
__device__ float g_q [BSZ*DD];
__device__ float g_kv[BSZ*DD];
__device__ float g_v [BSZ*DD];
__device__ float g_g [BSZ*DD];
__device__ float g_a [BSZ*2*DD];
__device__ float g_yr[BSZ*DD];
__device__ float g_yi[BSZ*DD];
__device__ float g_z [BSZ*DD];
__device__ float g_t1[BSZ*DD];
__device__ float g_x1[BSZ*DD];
__device__ float g_h [BSZ*FF];
__device__ float g_wt[15*MEL];     // transposed weights [N][K]
__device__ float g_Ar[BB*NC*DD], g_Ai[BB*NC*DD], g_Hr[BB*NC*DD], g_Hi[BB*NC*DD];
__device__ float g_Cr[BB*NC*DD], g_Ci[BB*NC*DD];
__device__ float g_gnstat[BB*GG*3];

// ---------------- helpers --------------------------------------------------
__device__ __forceinline__ void mma16(float* c,
        unsigned a0,unsigned a1,unsigned a2,unsigned a3,
        unsigned b0,unsigned b1){
    asm volatile(
      "mma.sync.aligned.m16n8k16.row.col.f32.bf16.bf16.f32 "
      "{%0,%1,%2,%3},{%4,%5,%6,%7},{%8,%9},{%0,%1,%2,%3};\n"
      : "+f"(c[0]),"+f"(c[1]),"+f"(c[2]),"+f"(c[3])
      : "r"(a0),"r"(a1),"r"(a2),"r"(a3),"r"(b0),"r"(b1));
}
__device__ __forceinline__ float gelu_f(float x){
    float x3 = x*x*x;
    return 0.5f*x*(1.0f + tanhf(0.7978845608028654f*(x + 0.044715f*x3)));
}
__device__ __forceinline__ void split2(float x0, float x1, unsigned &h, unsigned &l){
    __nv_bfloat16 h0 = __float2bfloat16(x0), h1 = __float2bfloat16(x1);
    float r0 = x0 - __bfloat162float(h0);
    float r1 = x1 - __bfloat162float(h1);
    __nv_bfloat16 l0 = __float2bfloat16(r0), l1 = __float2bfloat16(r1);
    h = ((unsigned)__bfloat16_as_ushort(h1) << 16) | (unsigned)__bfloat16_as_ushort(h0);
    l = ((unsigned)__bfloat16_as_ushort(l1) << 16) | (unsigned)__bfloat16_as_ushort(l0);
}
__device__ __forceinline__ float blockSum256(float v){
    __shared__ float sh[8];
    __shared__ float tot;
    #pragma unroll
    for (int off=16; off>0; off>>=1) v += __shfl_down_sync(0xffffffffu, v, off);
    if ((threadIdx.x & 31) == 0) sh[threadIdx.x>>5] = v;
    __syncthreads();
    if (threadIdx.x == 0){
        float t = 0.f;
        #pragma unroll
        for (int i=0;i<8;i++) t += sh[i];
        tot = t;
    }
    __syncthreads();
    float r = tot;
    __syncthreads();
    return r;
}

// ---------------- weight transpose: in[R][C] -> out[C][R] -------------------
__global__ void tpose(const float* __restrict__ in, float* __restrict__ out,
                      int R, int C){
    __shared__ float t[32][33];
    int bx = blockIdx.x*32, by = blockIdx.y*32;
    int x = bx + threadIdx.x;
    #pragma unroll
    for (int j=0;j<4;j++){
        int y = by + threadIdx.y + j*8;
        t[threadIdx.y + j*8][threadIdx.x] = in[(size_t)y*C + x];
    }
    __syncthreads();
    int xo = by + threadIdx.x;
    #pragma unroll
    for (int j=0;j<4;j++){
        int yo = bx + threadIdx.y + j*8;
        out[(size_t)yo*R + xo] = t[threadIdx.x][threadIdx.y + j*8];
    }
}

// ---------------- 3xBF16 GEMM, 512 threads, warp tile 32x32 -----------------
// C[M,N] = A[M,K] @ B[K,N] with Bt[n][k] = B[k][n].
// 128x128 block tile, k-step 32, double-buffered via registers.
#define PLN (128*40)
template<int ACT>
__global__ void __launch_bounds__(512)
gemm_bf3(const float* __restrict__ A, const float* __restrict__ Bt,
         float* __restrict__ C, int M, int N, int K,
         const float* __restrict__ bias, const float* __restrict__ resid)
{
    extern __shared__ __nv_bfloat16 dsm[];   // 8 planes of 128x40 bf16

    const int tid  = threadIdx.x;
    const int warp = tid >> 5, lane = tid & 31;
    const int grp  = lane >> 2, tq  = lane & 3;
    const int wm   = warp & 3;      // 4 warps along M (32 rows each)
    const int wn   = warp >> 2;     // 4 warps along N (32 cols each)
    const int m0   = blockIdx.y * 128, n0 = blockIdx.x * 128;
    const int lr   = tid >> 3;      // load row 0..63 (and +64)
    const int lc4  = tid & 7;       // load col group (float4)

    float acc[2][4][4];
    #pragma unroll
    for (int i=0;i<2;i++)
      #pragma unroll
      for (int j=0;j<4;j++)
        #pragma unroll
        for (int r=0;r<4;r++) acc[i][j][r] = 0.f;

    float4 ra[2], rb[2];
    const float* Arow = A  + (size_t)(m0 + lr)*K + lc4*4;
    const float* Brow = Bt + (size_t)(n0 + lr)*K + lc4*4;

    // prologue: load tile 0
    #pragma unroll
    for (int i=0;i<2;i++){
        ra[i] = *reinterpret_cast<const float4*>(Arow + (size_t)(i*64)*K);
        rb[i] = *reinterpret_cast<const float4*>(Brow + (size_t)(i*64)*K);
    }
    {   // cvt + store to buffer 0
        __nv_bfloat16* Ah = dsm + 0*PLN; __nv_bfloat16* Al = dsm + 1*PLN;
        __nv_bfloat16* Bh = dsm + 2*PLN; __nv_bfloat16* Bl = dsm + 3*PLN;
        #pragma unroll
        for (int i=0;i<2;i++){
            int off = (lr + i*64)*40 + lc4*4;
            unsigned h0,l0,h1,l1;
            split2(ra[i].x, ra[i].y, h0, l0);
            split2(ra[i].z, ra[i].w, h1, l1);
            *reinterpret_cast<uint2*>(Ah+off) = make_uint2(h0,h1);
            *reinterpret_cast<uint2*>(Al+off) = make_uint2(l0,l1);
            split2(rb[i].x, rb[i].y, h0, l0);
            split2(rb[i].z, rb[i].w, h1, l1);
            *reinterpret_cast<uint2*>(Bh+off) = make_uint2(h0,h1);
            *reinterpret_cast<uint2*>(Bl+off) = make_uint2(l0,l1);
        }
    }
    __syncthreads();

    const int nIter = K >> 5;
    for (int it = 0; it < nIter; it++){
        int buf = it & 1;
        const __nv_bfloat16* Ah = dsm + (buf*4+0)*PLN;
        const __nv_bfloat16* Al = dsm + (buf*4+1)*PLN;
        const __nv_bfloat16* Bh = dsm + (buf*4+2)*PLN;
        const __nv_bfloat16* Bl = dsm + (buf*4+3)*PLN;

        // issue next tile's global loads (hidden behind compute)
        bool more = (it+1 < nIter);
        if (more){
            const float* An = Arow + (size_t)(it+1)*32;
            const float* Bn = Brow + (size_t)(it+1)*32;
            #pragma unroll
            for (int i=0;i<2;i++){
                ra[i] = *reinterpret_cast<const float4*>(An + (size_t)(i*64)*K);
                rb[i] = *reinterpret_cast<const float4*>(Bn + (size_t)(i*64)*K);
            }
        }

        #pragma unroll
        for (int ks=0; ks<2; ks++){
            const int kk = ks*16 + tq*2;
            unsigned ah[2][4], al2[2][4];
            #pragma unroll
            for (int mt=0; mt<2; mt++){
                int r0 = wm*32 + mt*16 + grp;
                ah[mt][0]  = *reinterpret_cast<const unsigned*>(Ah + r0*40     + kk);
                ah[mt][1]  = *reinterpret_cast<const unsigned*>(Ah + (r0+8)*40 + kk);
                ah[mt][2]  = *reinterpret_cast<const unsigned*>(Ah + r0*40     + kk+8);
                ah[mt][3]  = *reinterpret_cast<const unsigned*>(Ah + (r0+8)*40 + kk+8);
                al2[mt][0] = *reinterpret_cast<const unsigned*>(Al + r0*40     + kk);
                al2[mt][1] = *reinterpret_cast<const unsigned*>(Al + (r0+8)*40 + kk);
                al2[mt][2] = *reinterpret_cast<const unsigned*>(Al + r0*40     + kk+8);
                al2[mt][3] = *reinterpret_cast<const unsigned*>(Al + (r0+8)*40 + kk+8);
            }
            unsigned bh2[4][2], bl2[4][2];
            #pragma unroll
            for (int nt=0; nt<4; nt++){
                int c = wn*32 + nt*8 + grp;
                bh2[nt][0] = *reinterpret_cast<const unsigned*>(Bh + c*40 + kk);
                bh2[nt][1] = *reinterpret_cast<const unsigned*>(Bh + c*40 + kk+8);
                bl2[nt][0] = *reinterpret_cast<const unsigned*>(Bl + c*40 + kk);
                bl2[nt][1] = *reinterpret_cast<const unsigned*>(Bl + c*40 + kk+8);
            }
            #pragma unroll
            for (int mt=0; mt<2; mt++)
              #pragma unroll
              for (int nt=0; nt<4; nt++){
                  mma16(acc[mt][nt], ah[mt][0],ah[mt][1],ah[mt][2],ah[mt][3],
                                     bh2[nt][0],bh2[nt][1]);
                  mma16(acc[mt][nt], ah[mt][0],ah[mt][1],ah[mt][2],ah[mt][3],
                                     bl2[nt][0],bl2[nt][1]);
                  mma16(acc[mt][nt], al2[mt][0],al2[mt][1],al2[mt][2],al2[mt][3],
                                     bh2[nt][0],bh2[nt][1]);
              }
        }

        if (more){
            int nb = (it+1) & 1;
            __nv_bfloat16* nAh = dsm + (nb*4+0)*PLN; __nv_bfloat16* nAl = dsm + (nb*4+1)*PLN;
            __nv_bfloat16* nBh = dsm + (nb*4+2)*PLN; __nv_bfloat16* nBl = dsm + (nb*4+3)*PLN;
            #pragma unroll
            for (int i=0;i<2;i++){
                int off = (lr + i*64)*40 + lc4*4;
                unsigned h0,l0,h1,l1;
                split2(ra[i].x, ra[i].y, h0, l0);
                split2(ra[i].z, ra[i].w, h1, l1);
                *reinterpret_cast<uint2*>(nAh+off) = make_uint2(h0,h1);
                *reinterpret_cast<uint2*>(nAl+off) = make_uint2(l0,l1);
                split2(rb[i].x, rb[i].y, h0, l0);
                split2(rb[i].z, rb[i].w, h1, l1);
                *reinterpret_cast<uint2*>(nBh+off) = make_uint2(h0,h1);
                *reinterpret_cast<uint2*>(nBl+off) = make_uint2(l0,l1);
            }
            __syncthreads();
        }
    }

    // epilogue
    #pragma unroll
    for (int mt=0; mt<2; mt++)
      #pragma unroll
      for (int nt=0; nt<4; nt++){
          int row = m0 + wm*32 + mt*16 + grp;
          int col = n0 + wn*32 + nt*8 + tq*2;
          #pragma unroll
          for (int h=0; h<2; h++){
              int r = row + h*8;
              float v0 = acc[mt][nt][h*2+0];
              float v1 = acc[mt][nt][h*2+1];
              if (bias){ v0 += bias[col]; v1 += bias[col+1]; }
              if (ACT == 1){ v0 = gelu_f(v0); v1 = gelu_f(v1); }
              if (resid){
                  size_t o = (size_t)r*N + col;
                  v0 += resid[o]; v1 += resid[o+1];
              }
              float2 w; w.x = v0; w.y = v1;
              *reinterpret_cast<float2*>(C + (size_t)r*N + col) = w;
          }
      }
}

// ---------------- elementwise prep ------------------------------------------
__global__ void prep_kernel(){
    int i = blockIdx.x*256 + threadIdx.x;
    int row = i / DD, d = i % DD;
    size_t abase = (size_t)row*2*DD;
    float ar = g_a[abase + d], ai = g_a[abase + DD + d];
    float mag = sqrtf(ar*ar + ai*ai);
    float sig = 1.f/(1.f + expf(-mag));
    float acr, aci;
    if (mag > 1e-30f){ float s = sig/mag; acr = ar*s; aci = ai*s; }
    else             { acr = sig; aci = 0.f; }
    g_a[abase + d] = acr;
    g_a[abase + DD + d] = aci;
    g_kv[i] = g_kv[i] * g_v[i];
}

// ---------------- 3-phase chunked complex scan -------------------------------
__global__ void scan1(){
    int t = blockIdx.x*256 + threadIdx.x;
    int d = t % DD;
    int t2 = t / DD;
    int chunk = t2 % NC;
    int b = t2 / NC;
    float Ar=1.f, Ai=0.f, Hr=0.f, Hi=0.f;
    size_t srow = (size_t)(b*SS + chunk*CL);
    for (int u=0; u<CL; u++){
        size_t row = srow + u;
        float ar = g_a[row*2*DD + d], ai = g_a[row*2*DD + DD + d];
        float kv = g_kv[row*DD + d];
        float nAr = ar*Ar - ai*Ai,      nAi = ar*Ai + ai*Ar;
        float nHr = ar*Hr - ai*Hi + kv, nHi = ar*Hi + ai*Hr;
        Ar=nAr; Ai=nAi; Hr=nHr; Hi=nHi;
    }
    size_t o = (size_t)(b*NC + chunk)*DD + d;
    g_Ar[o]=Ar; g_Ai[o]=Ai; g_Hr[o]=Hr; g_Hi[o]=Hi;
}
__global__ void scan2(){
    int t = blockIdx.x*256 + threadIdx.x;
    if (t >= BB*DD) return;
    int d = t % DD, b = t / DD;
    float cr=0.f, ci=0.f;
    for (int c=0; c<NC; c++){
        size_t o = (size_t)(b*NC + c)*DD + d;
        g_Cr[o]=cr; g_Ci[o]=ci;
        float Ar=g_Ar[o], Ai=g_Ai[o], Hr=g_Hr[o], Hi=g_Hi[o];
        float nr = Ar*cr - Ai*ci + Hr;
        float ni = Ar*ci + Ai*cr + Hi;
        cr=nr; ci=ni;
    }
}
__global__ void scan3(){
    int t = blockIdx.x*256 + threadIdx.x;
    int d = t % DD;
    int t2 = t / DD;
    int chunk = t2 % NC;
    int b = t2 / NC;
    size_t o = (size_t)(b*NC + chunk)*DD + d;
    float hr = g_Cr[o], hi = g_Ci[o];
    size_t srow = (size_t)(b*SS + chunk*CL);
    for (int u=0; u<CL; u++){
        size_t row = srow + u;
        float ar = g_a[row*2*DD + d], ai = g_a[row*2*DD + DD + d];
        float kv = g_kv[row*DD + d];
        float nhr = ar*hr - ai*hi + kv;
        float nhi = ar*hi + ai*hr;
        hr=nhr; hi=nhi;
        float q = g_q[row*DD + d];
        g_yr[row*DD + d] = q*hr;
        g_yi[row*DD + d] = q*hi;
    }
}

// ---------------- complex GroupNorm stats + gated apply ----------------------
__global__ void gnstats(){
    int gi = blockIdx.x;
    int b = gi / GG, g = gi % GG;
    const int DG = DD/GG;
    float sr=0.f, si=0.f, s2=0.f;
    for (int idx = threadIdx.x; idx < SS*DG; idx += blockDim.x){
        int s = idx / DG, dc = idx % DG;
        size_t o = ((size_t)(b*SS + s))*DD + g*DG + dc;
        float yr = g_yr[o], yi = g_yi[o];
        sr += yr; si += yi; s2 += yr*yr + yi*yi;
    }
    sr = blockSum256(sr);
    si = blockSum256(si);
    s2 = blockSum256(s2);
    if (threadIdx.x == 0){
        const float cnt = (float)(SS*DG);
        float mr = sr/cnt, mi = si/cnt;
        float var = s2/cnt - mr*mr - mi*mi;
        g_gnstat[gi*3+0] = mr;
        g_gnstat[gi*3+1] = mi;
        g_gnstat[gi*3+2] = rsqrtf(var + EPSV);
    }
}
__global__ void gapply(const float* __restrict__ gn_scale,
                       const float* __restrict__ gn_bias){
    int i = blockIdx.x*256 + threadIdx.x;
    int row = i / DD, d = i % DD;
    int b = row / SS;
    int gi = b*GG + d/(DD/GG);
    float mr  = g_gnstat[gi*3+0];
    float inv = g_gnstat[gi*3+2];
    float yn = (g_yr[i] - mr)*inv*gn_scale[d] + gn_bias[d];
    float gv = g_g[i];
    float silu = gv / (1.f + expf(-gv));
    g_z[i] = yn * silu;
}

// ---------------- rowwise LayerNorm ------------------------------------------
__global__ void ln_kernel(const float* __restrict__ xin,
                          const float* __restrict__ addin,
                          float* __restrict__ out,
                          const float* __restrict__ sc,
                          const float* __restrict__ bi){
    int row = blockIdx.x;
    int tid = threadIdx.x;
    size_t base = (size_t)row*DD + tid*4;
    float4 v = *reinterpret_cast<const float4*>(xin + base);
    if (addin){
        float4 w = *reinterpret_cast<const float4*>(addin + base);
        v.x += w.x; v.y += w.y; v.z += w.z; v.w += w.w;
    }
    float s = v.x + v.y + v.z + v.w;
    float mu = blockSum256(s) * (1.f/DD);
    float dx = v.x-mu, dy = v.y-mu, dz = v.z-mu, dw = v.w-mu;
    float sq = dx*dx + dy*dy + dz*dz + dw*dw;
    float var = blockSum256(sq) * (1.f/DD);
    float inv = rsqrtf(var + EPSV);
    int c = tid*4;
    float4 o;
    o.x = dx*inv*sc[c+0] + bi[c+0];
    o.y = dy*inv*sc[c+1] + bi[c+1];
    o.z = dz*inv*sc[c+2] + bi[c+2];
    o.w = dw*inv*sc[c+3] + bi[c+3];
    *reinterpret_cast<float4*>(out + base) = o;
}

// ---------------- launch ------------------------------------------------------
extern "C" void kernel_launch(void* const* d_in, const int* in_sizes, int n_in,
                              void* d_out, int out_size){
    const float* x         = (const float*)d_in[0];
    const float* Wq        = (const float*)d_in[1];
    const float* Wk        = (const float*)d_in[2];
    const float* Wv        = (const float*)d_in[3];
    const float* Wa        = (const float*)d_in[4];
    const float* Wg        = (const float*)d_in[5];
    const float* Wo        = (const float*)d_in[6];
    const float* gn_scale  = (const float*)d_in[7];
    const float* gn_bias   = (const float*)d_in[8];
    const float* ln1_scale = (const float*)d_in[9];
    const float* ln1_bias  = (const float*)d_in[10];
    const float* W1        = (const float*)d_in[11];
    const float* b1        = (const float*)d_in[12];
    const float* W2        = (const float*)d_in[13];
    const float* b2        = (const float*)d_in[14];
    const float* ln2_scale = (const float*)d_in[15];
    const float* ln2_bias  = (const float*)d_in[16];
    float* out = (float*)d_out;

    float *pq,*pkv,*pv,*pg,*pa,*pz,*pt1,*px1,*ph,*pwt;
    cudaGetSymbolAddress((void**)&pq,  g_q);
    cudaGetSymbolAddress((void**)&pkv, g_kv);
    cudaGetSymbolAddress((void**)&pv,  g_v);
    cudaGetSymbolAddress((void**)&pg,  g_g);
    cudaGetSymbolAddress((void**)&pa,  g_a);
    cudaGetSymbolAddress((void**)&pz,  g_z);
    cudaGetSymbolAddress((void**)&pt1, g_t1);
    cudaGetSymbolAddress((void**)&px1, g_x1);
    cudaGetSymbolAddress((void**)&ph,  g_h);
    cudaGetSymbolAddress((void**)&pwt, g_wt);

    float* wtq = pwt + 0*MEL;
    float* wtk = pwt + 1*MEL;
    float* wtv = pwt + 2*MEL;
    float* wtg = pwt + 3*MEL;
    float* wto = pwt + 4*MEL;
    float* wt1 = pwt + 5*MEL;   // [FF][DD]
    float* wt2 = pwt + 9*MEL;   // [DD][FF]
    float* wta = pwt + 13*MEL;  // [2DD][DD]

    static int smem_set = 0;
    const int GEMM_SMEM = 8*PLN*2;   // 81920 bytes
    if (!smem_set){
        cudaFuncSetAttribute(gemm_bf3<0>, cudaFuncAttributeMaxDynamicSharedMemorySize, GEMM_SMEM);
        cudaFuncSetAttribute(gemm_bf3<1>, cudaFuncAttributeMaxDynamicSharedMemorySize, GEMM_SMEM);
        smem_set = 1;
    }

    dim3 tb(32,8);
    tpose<<<dim3(DD/32, DD/32), tb>>>(Wq, wtq, DD, DD);
    tpose<<<dim3(DD/32, DD/32), tb>>>(Wk, wtk, DD, DD);
    tpose<<<dim3(DD/32, DD/32), tb>>>(Wv, wtv, DD, DD);
    tpose<<<dim3(DD/32, DD/32), tb>>>(Wg, wtg, DD, DD);
    tpose<<<dim3(DD/32, DD/32), tb>>>(Wo, wto, DD, DD);
    tpose<<<dim3(FF/32, DD/32), tb>>>(W1, wt1, DD, FF);
    tpose<<<dim3(DD/32, FF/32), tb>>>(W2, wt2, FF, DD);
    tpose<<<dim3(2*DD/32, DD/32), tb>>>(Wa, wta, DD, 2*DD);

    dim3 blk(512);
    dim3 gD (DD/128,   BSZ/128);
    dim3 gA (2*DD/128, BSZ/128);
    dim3 gF (FF/128,   BSZ/128);

    gemm_bf3<0><<<gD, blk, GEMM_SMEM>>>(x, wtq, pq,  BSZ, DD,   DD, nullptr, nullptr);
    gemm_bf3<0><<<gD, blk, GEMM_SMEM>>>(x, wtk, pkv, BSZ, DD,   DD, nullptr, nullptr);
    gemm_bf3<0><<<gD, blk, GEMM_SMEM>>>(x, wtv, pv,  BSZ, DD,   DD, nullptr, nullptr);
    gemm_bf3<0><<<gD, blk, GEMM_SMEM>>>(x, wtg, pg,  BSZ, DD,   DD, nullptr, nullptr);
    gemm_bf3<0><<<gA, blk, GEMM_SMEM>>>(x, wta, pa,  BSZ, 2*DD, DD, nullptr, nullptr);

    prep_kernel<<<BSZ*DD/256, 256>>>();
    scan1<<<BB*DD*NC/256, 256>>>();
    scan2<<<(BB*DD+255)/256, 256>>>();
    scan3<<<BB*DD*NC/256, 256>>>();
    gnstats<<<BB*GG, 256>>>();
    gapply<<<BSZ*DD/256, 256>>>(gn_scale, gn_bias);

    gemm_bf3<0><<<gD, blk, GEMM_SMEM>>>(pz, wto, pt1, BSZ, DD, DD, nullptr, nullptr);
    ln_kernel<<<BSZ, 256>>>(x, pt1, px1, ln1_scale, ln1_bias);

    gemm_bf3<1><<<gF, blk, GEMM_SMEM>>>(px1, wt1, ph,  BSZ, FF, DD, b1, nullptr);
    gemm_bf3<0><<<gD, blk, GEMM_SMEM>>>(ph,  wt2, pt1, BSZ, DD, FF, b2, px1);

    ln_kernel<<<BSZ, 256>>>(pt1, nullptr, out, ln2_scale, ln2_bias);
}

// round 5
// speedup vs baseline: 2.2846x; 1.3004x over previous
#include <cuda_runtime.h>
#include <cuda_bf16.h>
#include <cstdint>
#include <math.h>

#define BB 4
#define SS 4096
#define DD 1024
#define FF 4096
#define GG 32
#define BSZ (BB*SS)          // 16384 tokens
#define NC 64                // chunks per sequence
#define CL (SS/NC)           // 64 steps per chunk
#define MEL (1024*1024)
static __device__ __constant__ float EPSV = 1e-6f;

// ---------------- fp32 scratch ----------------------------------------------
__device__ float g_q [BSZ*DD];
__device__ float g_kv[BSZ*DD];
__device__ float g_v [BSZ*DD];
__device__ float g_g [BSZ*DD];
__device__ float g_a [BSZ*2*DD];
__device__ float g_yr[BSZ*DD];
__device__ float g_yi[BSZ*DD];
__device__ float g_t1[BSZ*DD];
__device__ float g_x1[BSZ*DD];
__device__ float g_Ar[BB*NC*DD], g_Ai[BB*NC*DD], g_Hr[BB*NC*DD], g_Hi[BB*NC*DD];
__device__ float g_Cr[BB*NC*DD], g_Ci[BB*NC*DD];
__device__ float g_gnstat[BB*GG*3];

// ---------------- bf16 hi/lo planes (one big pool, offsets in MEL units) ----
// XH 0, XL 16, ZH 32, ZL 48, X1H 64, X1L 80, HH 96, HL 160,
// WQH 224, WQL 225, WKH 226, WKL 227, WVH 228, WVL 229, WGH 230, WGL 231,
// WOH 232, WOL 233, WAH 234(2), WAL 236(2), W1H 238(4), W1L 242(4),
// W2H 246(4), W2L 250(4)  -> total 254 MEL
__device__ __nv_bfloat16 g_bf[254*MEL];
#define OF_XH  (0*MEL)
#define OF_XL  (16*MEL)
#define OF_ZH  (32*MEL)
#define OF_ZL  (48*MEL)
#define OF_X1H (64*MEL)
#define OF_X1L (80*MEL)
#define OF_HH  (96*MEL)
#define OF_HL  (160*MEL)
#define OF_WQH (224*MEL)
#define OF_WQL (225*MEL)
#define OF_WKH (226*MEL)
#define OF_WKL (227*MEL)
#define OF_WVH (228*MEL)
#define OF_WVL (229*MEL)
#define OF_WGH (230*MEL)
#define OF_WGL (231*MEL)
#define OF_WOH (232*MEL)
#define OF_WOL (233*MEL)
#define OF_WAH (234*MEL)
#define OF_WAL (236*MEL)
#define OF_W1H (238*MEL)
#define OF_W1L (242*MEL)
#define OF_W2H (246*MEL)
#define OF_W2L (250*MEL)

// ---------------- helpers ----------------------------------------------------
__device__ __forceinline__ uint32_t smem_u32(const void* p) {
    uint32_t a;
    asm("{ .reg .u64 t; cvta.to.shared.u64 t, %1; cvt.u32.u64 %0, t; }"
        : "=r"(a) : "l"(p));
    return a;
}
__device__ __forceinline__ void mma16(float* c,
        unsigned a0,unsigned a1,unsigned a2,unsigned a3,
        unsigned b0,unsigned b1){
    asm volatile(
      "mma.sync.aligned.m16n8k16.row.col.f32.bf16.bf16.f32 "
      "{%0,%1,%2,%3},{%4,%5,%6,%7},{%8,%9},{%0,%1,%2,%3};\n"
      : "+f"(c[0]),"+f"(c[1]),"+f"(c[2]),"+f"(c[3])
      : "r"(a0),"r"(a1),"r"(a2),"r"(a3),"r"(b0),"r"(b1));
}
__device__ __forceinline__ void ldmx4(unsigned* r, uint32_t addr){
    asm volatile("ldmatrix.sync.aligned.m8n8.x4.shared.b16 {%0,%1,%2,%3}, [%4];"
      : "=r"(r[0]),"=r"(r[1]),"=r"(r[2]),"=r"(r[3]) : "r"(addr));
}
__device__ __forceinline__ float gelu_f(float x){
    float x3 = x*x*x;
    return 0.5f*x*(1.0f + tanhf(0.7978845608028654f*(x + 0.044715f*x3)));
}
__device__ __forceinline__ void split2(float x0, float x1, unsigned &h, unsigned &l){
    __nv_bfloat16 h0 = __float2bfloat16(x0), h1 = __float2bfloat16(x1);
    float r0 = x0 - __bfloat162float(h0);
    float r1 = x1 - __bfloat162float(h1);
    __nv_bfloat16 l0 = __float2bfloat16(r0), l1 = __float2bfloat16(r1);
    h = ((unsigned)__bfloat16_as_ushort(h1) << 16) | (unsigned)__bfloat16_as_ushort(h0);
    l = ((unsigned)__bfloat16_as_ushort(l1) << 16) | (unsigned)__bfloat16_as_ushort(l0);
}
__device__ __forceinline__ float blockSum256(float v){
    __shared__ float sh[8];
    __shared__ float tot;
    #pragma unroll
    for (int off=16; off>0; off>>=1) v += __shfl_down_sync(0xffffffffu, v, off);
    if ((threadIdx.x & 31) == 0) sh[threadIdx.x>>5] = v;
    __syncthreads();
    if (threadIdx.x == 0){
        float t = 0.f;
        #pragma unroll
        for (int i=0;i<8;i++) t += sh[i];
        tot = t;
    }
    __syncthreads();
    float r = tot;
    __syncthreads();
    return r;
}

// ---------------- weight transpose + split: fp32[R][C] -> bf16 planes [C][R] -
__global__ void wsplit(const float* __restrict__ in,
                       __nv_bfloat16* __restrict__ oh,
                       __nv_bfloat16* __restrict__ ol, int R, int C){
    __shared__ float t[32][33];
    int bx = blockIdx.x*32, by = blockIdx.y*32;
    int x = bx + threadIdx.x;
    #pragma unroll
    for (int j=0;j<4;j++){
        int y = by + threadIdx.y + j*8;
        t[threadIdx.y + j*8][threadIdx.x] = in[(size_t)y*C + x];
    }
    __syncthreads();
    int xo = by + threadIdx.x;
    #pragma unroll
    for (int j=0;j<4;j++){
        int yo = bx + threadIdx.y + j*8;
        float v = t[threadIdx.x][threadIdx.y + j*8];
        __nv_bfloat16 h = __float2bfloat16(v);
        __nv_bfloat16 l = __float2bfloat16(v - __bfloat162float(h));
        oh[(size_t)yo*R + xo] = h;
        ol[(size_t)yo*R + xo] = l;
    }
}

// ---------------- activation split: fp32 -> bf16 hi/lo ----------------------
__global__ void asplit(const float* __restrict__ in,
                       __nv_bfloat16* __restrict__ oh,
                       __nv_bfloat16* __restrict__ ol){
    size_t i = ((size_t)blockIdx.x*256 + threadIdx.x)*4;
    float4 v = *reinterpret_cast<const float4*>(in + i);
    unsigned h0,l0,h1,l1;
    split2(v.x, v.y, h0, l0);
    split2(v.z, v.w, h1, l1);
    *reinterpret_cast<uint2*>(oh + i) = make_uint2(h0, h1);
    *reinterpret_cast<uint2*>(ol + i) = make_uint2(l0, l1);
}

// ---------------- pure-bf16 3-term GEMM with ldmatrix ------------------------
// C = A @ B^T(planes), A planes [M][K] bf16 hi/lo, B planes [N][K] bf16 hi/lo.
// 128x128 tile, 512 threads (16 warps, warp tile 32x32), k-step 32,
// double-buffered smem, rows padded to 40 bf16 (80B) => conflict-free LDSM.
#define BPLN (128*40)           // bf16 elements per plane
#define GSMEM (8*BPLN*2)        // 81920 bytes

template<int ACT, int OUTBF>
__global__ void __launch_bounds__(512,1)
gemm_bf(const __nv_bfloat16* __restrict__ Ah, const __nv_bfloat16* __restrict__ Al,
        const __nv_bfloat16* __restrict__ Bh, const __nv_bfloat16* __restrict__ Bl,
        float* __restrict__ C,
        __nv_bfloat16* __restrict__ Ch, __nv_bfloat16* __restrict__ Cl,
        int M, int N, int K,
        const float* __restrict__ bias, const float* __restrict__ resid)
{
    extern __shared__ __nv_bfloat16 sm[];
    const uint32_t sb = smem_u32(sm);
    const int tid  = threadIdx.x;
    const int warp = tid >> 5, lane = tid & 31;
    const int grp  = lane >> 2, tq = lane & 3;
    const int wm   = warp & 3;       // 4 warps along M
    const int wn   = warp >> 2;      // 4 warps along N
    const int m0   = blockIdx.y * 128, n0 = blockIdx.x * 128;
    const int lr   = tid >> 2;       // 0..127
    const int lc   = tid & 3;        // 16B group (8 bf16)

    float acc[2][4][4];
    #pragma unroll
    for (int i=0;i<2;i++)
      #pragma unroll
      for (int j=0;j<4;j++)
        #pragma unroll
        for (int r=0;r<4;r++) acc[i][j][r] = 0.f;

    const __nv_bfloat16* gAh = Ah + (size_t)(m0+lr)*K + lc*8;
    const __nv_bfloat16* gAl = Al + (size_t)(m0+lr)*K + lc*8;
    const __nv_bfloat16* gBh = Bh + (size_t)(n0+lr)*K + lc*8;
    const __nv_bfloat16* gBl = Bl + (size_t)(n0+lr)*K + lc*8;

    uint4 rAh, rAl, rBh, rBl;
    // prologue: tile 0
    rAh = *reinterpret_cast<const uint4*>(gAh);
    rAl = *reinterpret_cast<const uint4*>(gAl);
    rBh = *reinterpret_cast<const uint4*>(gBh);
    rBl = *reinterpret_cast<const uint4*>(gBl);
    {
        int off = lr*40 + lc*8;
        *reinterpret_cast<uint4*>(sm + 0*BPLN + off) = rAh;
        *reinterpret_cast<uint4*>(sm + 1*BPLN + off) = rAl;
        *reinterpret_cast<uint4*>(sm + 2*BPLN + off) = rBh;
        *reinterpret_cast<uint4*>(sm + 3*BPLN + off) = rBl;
    }
    __syncthreads();

    // ldmatrix lane geometry
    const int a_row = ((lane>>3)&1)*8 + (lane&7);
    const int a_k   = (lane>>4)*8;
    const int b_row = ((lane>>4)&1)*8 + (lane&7);
    const int b_k   = ((lane>>3)&1)*8;

    const int nkt = K >> 5;
    for (int it = 0; it < nkt; it++){
        int b = it & 1;
        if (it+1 < nkt){
            rAh = *reinterpret_cast<const uint4*>(gAh + (it+1)*32);
            rAl = *reinterpret_cast<const uint4*>(gAl + (it+1)*32);
            rBh = *reinterpret_cast<const uint4*>(gBh + (it+1)*32);
            rBl = *reinterpret_cast<const uint4*>(gBl + (it+1)*32);
        }
        uint32_t baseAh = sb + (uint32_t)(b*4+0)*BPLN*2;
        uint32_t baseAl = sb + (uint32_t)(b*4+1)*BPLN*2;
        uint32_t baseBh = sb + (uint32_t)(b*4+2)*BPLN*2;
        uint32_t baseBl = sb + (uint32_t)(b*4+3)*BPLN*2;

        #pragma unroll
        for (int ks=0; ks<2; ks++){
            unsigned ah[2][4], al[2][4], bh[2][4], bl[2][4];
            #pragma unroll
            for (int mt=0; mt<2; mt++){
                uint32_t o = (uint32_t)((wm*32 + mt*16 + a_row)*40 + ks*16 + a_k)*2;
                ldmx4(ah[mt], baseAh + o);
                ldmx4(al[mt], baseAl + o);
            }
            #pragma unroll
            for (int np=0; np<2; np++){
                uint32_t o = (uint32_t)((wn*32 + np*16 + b_row)*40 + ks*16 + b_k)*2;
                ldmx4(bh[np], baseBh + o);
                ldmx4(bl[np], baseBl + o);
            }
            #pragma unroll
            for (int mt=0; mt<2; mt++)
              #pragma unroll
              for (int nt=0; nt<4; nt++){
                  int np = nt>>1, hf = (nt&1)*2;
                  mma16(acc[mt][nt], ah[mt][0],ah[mt][1],ah[mt][2],ah[mt][3],
                                     bh[np][hf], bh[np][hf+1]);
                  mma16(acc[mt][nt], ah[mt][0],ah[mt][1],ah[mt][2],ah[mt][3],
                                     bl[np][hf], bl[np][hf+1]);
                  mma16(acc[mt][nt], al[mt][0],al[mt][1],al[mt][2],al[mt][3],
                                     bh[np][hf], bh[np][hf+1]);
              }
        }

        if (it+1 < nkt){
            int nb = (it+1) & 1;
            int off = lr*40 + lc*8;
            *reinterpret_cast<uint4*>(sm + (nb*4+0)*BPLN + off) = rAh;
            *reinterpret_cast<uint4*>(sm + (nb*4+1)*BPLN + off) = rAl;
            *reinterpret_cast<uint4*>(sm + (nb*4+2)*BPLN + off) = rBh;
            *reinterpret_cast<uint4*>(sm + (nb*4+3)*BPLN + off) = rBl;
            __syncthreads();
        }
    }

    // epilogue
    #pragma unroll
    for (int mt=0; mt<2; mt++)
      #pragma unroll
      for (int nt=0; nt<4; nt++){
          int row = m0 + wm*32 + mt*16 + grp;
          int col = n0 + wn*32 + nt*8 + tq*2;
          #pragma unroll
          for (int h=0; h<2; h++){
              int r = row + h*8;
              float v0 = acc[mt][nt][h*2+0];
              float v1 = acc[mt][nt][h*2+1];
              if (bias){ v0 += bias[col]; v1 += bias[col+1]; }
              if (ACT == 1){ v0 = gelu_f(v0); v1 = gelu_f(v1); }
              if (resid){
                  size_t o = (size_t)r*N + col;
                  v0 += resid[o]; v1 += resid[o+1];
              }
              if (OUTBF){
                  unsigned ph, pl;
                  split2(v0, v1, ph, pl);
                  *reinterpret_cast<unsigned*>(Ch + (size_t)r*N + col) = ph;
                  *reinterpret_cast<unsigned*>(Cl + (size_t)r*N + col) = pl;
              } else {
                  float2 w; w.x = v0; w.y = v1;
                  *reinterpret_cast<float2*>(C + (size_t)r*N + col) = w;
              }
          }
      }
}

// ---------------- elementwise prep ------------------------------------------
__global__ void prep_kernel(){
    int i = blockIdx.x*256 + threadIdx.x;
    int row = i / DD, d = i % DD;
    size_t abase = (size_t)row*2*DD;
    float ar = g_a[abase + d], ai = g_a[abase + DD + d];
    float mag = sqrtf(ar*ar + ai*ai);
    float sig = 1.f/(1.f + expf(-mag));
    float acr, aci;
    if (mag > 1e-30f){ float s = sig/mag; acr = ar*s; aci = ai*s; }
    else             { acr = sig; aci = 0.f; }
    g_a[abase + d] = acr;
    g_a[abase + DD + d] = aci;
    g_kv[i] = g_kv[i] * g_v[i];
}

// ---------------- 3-phase chunked complex scan -------------------------------
__global__ void scan1(){
    int t = blockIdx.x*256 + threadIdx.x;
    int d = t % DD;
    int t2 = t / DD;
    int chunk = t2 % NC;
    int b = t2 / NC;
    float Ar=1.f, Ai=0.f, Hr=0.f, Hi=0.f;
    size_t srow = (size_t)(b*SS + chunk*CL);
    for (int u=0; u<CL; u++){
        size_t row = srow + u;
        float ar = g_a[row*2*DD + d], ai = g_a[row*2*DD + DD + d];
        float kv = g_kv[row*DD + d];
        float nAr = ar*Ar - ai*Ai,      nAi = ar*Ai + ai*Ar;
        float nHr = ar*Hr - ai*Hi + kv, nHi = ar*Hi + ai*Hr;
        Ar=nAr; Ai=nAi; Hr=nHr; Hi=nHi;
    }
    size_t o = (size_t)(b*NC + chunk)*DD + d;
    g_Ar[o]=Ar; g_Ai[o]=Ai; g_Hr[o]=Hr; g_Hi[o]=Hi;
}
__global__ void scan2(){
    int t = blockIdx.x*256 + threadIdx.x;
    if (t >= BB*DD) return;
    int d = t % DD, b = t / DD;
    float cr=0.f, ci=0.f;
    for (int c=0; c<NC; c++){
        size_t o = (size_t)(b*NC + c)*DD + d;
        g_Cr[o]=cr; g_Ci[o]=ci;
        float Ar=g_Ar[o], Ai=g_Ai[o], Hr=g_Hr[o], Hi=g_Hi[o];
        float nr = Ar*cr - Ai*ci + Hr;
        float ni = Ar*ci + Ai*cr + Hi;
        cr=nr; ci=ni;
    }
}
__global__ void scan3(){
    int t = blockIdx.x*256 + threadIdx.x;
    int d = t % DD;
    int t2 = t / DD;
    int chunk = t2 % NC;
    int b = t2 / NC;
    size_t o = (size_t)(b*NC + chunk)*DD + d;
    float hr = g_Cr[o], hi = g_Ci[o];
    size_t srow = (size_t)(b*SS + chunk*CL);
    for (int u=0; u<CL; u++){
        size_t row = srow + u;
        float ar = g_a[row*2*DD + d], ai = g_a[row*2*DD + DD + d];
        float kv = g_kv[row*DD + d];
        float nhr = ar*hr - ai*hi + kv;
        float nhi = ar*hi + ai*hr;
        hr=nhr; hi=nhi;
        float q = g_q[row*DD + d];
        g_yr[row*DD + d] = q*hr;
        g_yi[row*DD + d] = q*hi;
    }
}

// ---------------- complex GroupNorm stats + gated apply ----------------------
__global__ void gnstats(){
    int gi = blockIdx.x;
    int b = gi / GG, g = gi % GG;
    const int DG = DD/GG;
    float sr=0.f, si=0.f, s2=0.f;
    for (int idx = threadIdx.x; idx < SS*DG; idx += blockDim.x){
        int s = idx / DG, dc = idx % DG;
        size_t o = ((size_t)(b*SS + s))*DD + g*DG + dc;
        float yr = g_yr[o], yi = g_yi[o];
        sr += yr; si += yi; s2 += yr*yr + yi*yi;
    }
    sr = blockSum256(sr);
    si = blockSum256(si);
    s2 = blockSum256(s2);
    if (threadIdx.x == 0){
        const float cnt = (float)(SS*DG);
        float mr = sr/cnt, mi = si/cnt;
        float var = s2/cnt - mr*mr - mi*mi;
        g_gnstat[gi*3+0] = mr;
        g_gnstat[gi*3+1] = mi;
        g_gnstat[gi*3+2] = rsqrtf(var + EPSV);
    }
}
// gated apply -> writes bf16 hi/lo planes of z directly
__global__ void gapply(const float* __restrict__ gn_scale,
                       const float* __restrict__ gn_bias){
    int i = (blockIdx.x*256 + threadIdx.x)*2;
    int row = i / DD, d = i % DD;
    int b = row / SS;
    int gi = b*GG + d/(DD/GG);
    float mr  = g_gnstat[gi*3+0];
    float inv = g_gnstat[gi*3+2];
    float z0, z1;
    {
        float yn = (g_yr[i] - mr)*inv*gn_scale[d] + gn_bias[d];
        float gv = g_g[i];
        z0 = yn * (gv / (1.f + expf(-gv)));
    }
    {
        int d1 = d+1;
        int gi1 = b*GG + d1/(DD/GG);
        float mr1  = g_gnstat[gi1*3+0];
        float inv1 = g_gnstat[gi1*3+2];
        float yn = (g_yr[i+1] - mr1)*inv1*gn_scale[d1] + gn_bias[d1];
        float gv = g_g[i+1];
        z1 = yn * (gv / (1.f + expf(-gv)));
    }
    unsigned ph, pl;
    split2(z0, z1, ph, pl);
    *reinterpret_cast<unsigned*>(g_bf + OF_ZH + i) = ph;
    *reinterpret_cast<unsigned*>(g_bf + OF_ZL + i) = pl;
}

// ---------------- rowwise LayerNorm (optionally emits bf16 planes) -----------
template<int EMITBF>
__global__ void ln_kernel(const float* __restrict__ xin,
                          const float* __restrict__ addin,
                          float* __restrict__ out,
                          __nv_bfloat16* __restrict__ oh,
                          __nv_bfloat16* __restrict__ ol,
                          const float* __restrict__ sc,
                          const float* __restrict__ bi){
    int row = blockIdx.x;
    int tid = threadIdx.x;
    size_t base = (size_t)row*DD + tid*4;
    float4 v = *reinterpret_cast<const float4*>(xin + base);
    if (addin){
        float4 w = *reinterpret_cast<const float4*>(addin + base);
        v.x += w.x; v.y += w.y; v.z += w.z; v.w += w.w;
    }
    float s = v.x + v.y + v.z + v.w;
    float mu = blockSum256(s) * (1.f/DD);
    float dx = v.x-mu, dy = v.y-mu, dz = v.z-mu, dw = v.w-mu;
    float sq = dx*dx + dy*dy + dz*dz + dw*dw;
    float var = blockSum256(sq) * (1.f/DD);
    float inv = rsqrtf(var + EPSV);
    int c = tid*4;
    float4 o;
    o.x = dx*inv*sc[c+0] + bi[c+0];
    o.y = dy*inv*sc[c+1] + bi[c+1];
    o.z = dz*inv*sc[c+2] + bi[c+2];
    o.w = dw*inv*sc[c+3] + bi[c+3];
    if (out) *reinterpret_cast<float4*>(out + base) = o;
    if (EMITBF){
        unsigned h0,l0,h1,l1;
        split2(o.x, o.y, h0, l0);
        split2(o.z, o.w, h1, l1);
        *reinterpret_cast<uint2*>(oh + base) = make_uint2(h0, h1);
        *reinterpret_cast<uint2*>(ol + base) = make_uint2(l0, l1);
    }
}

// ---------------- launch ------------------------------------------------------
extern "C" void kernel_launch(void* const* d_in, const int* in_sizes, int n_in,
                              void* d_out, int out_size){
    const float* x         = (const float*)d_in[0];
    const float* Wq        = (const float*)d_in[1];
    const float* Wk        = (const float*)d_in[2];
    const float* Wv        = (const float*)d_in[3];
    const float* Wa        = (const float*)d_in[4];
    const float* Wg        = (const float*)d_in[5];
    const float* Wo        = (const float*)d_in[6];
    const float* gn_scale  = (const float*)d_in[7];
    const float* gn_bias   = (const float*)d_in[8];
    const float* ln1_scale = (const float*)d_in[9];
    const float* ln1_bias  = (const float*)d_in[10];
    const float* W1        = (const float*)d_in[11];
    const float* b1        = (const float*)d_in[12];
    const float* W2        = (const float*)d_in[13];
    const float* b2        = (const float*)d_in[14];
    const float* ln2_scale = (const float*)d_in[15];
    const float* ln2_bias  = (const float*)d_in[16];
    float* out = (float*)d_out;

    float *pq,*pkv,*pv,*pg,*pa,*pt1,*px1;
    __nv_bfloat16* pbf;
    cudaGetSymbolAddress((void**)&pq,  g_q);
    cudaGetSymbolAddress((void**)&pkv, g_kv);
    cudaGetSymbolAddress((void**)&pv,  g_v);
    cudaGetSymbolAddress((void**)&pg,  g_g);
    cudaGetSymbolAddress((void**)&pa,  g_a);
    cudaGetSymbolAddress((void**)&pt1, g_t1);
    cudaGetSymbolAddress((void**)&px1, g_x1);
    cudaGetSymbolAddress((void**)&pbf, g_bf);

    static int smem_set = 0;
    if (!smem_set){
        cudaFuncSetAttribute(gemm_bf<0,0>, cudaFuncAttributeMaxDynamicSharedMemorySize, GSMEM);
        cudaFuncSetAttribute(gemm_bf<1,1>, cudaFuncAttributeMaxDynamicSharedMemorySize, GSMEM);
        smem_set = 1;
    }

    dim3 tb(32,8);
    dim3 blk(512);
    dim3 gD (DD/128,   BSZ/128);
    dim3 gA (2*DD/128, BSZ/128);
    dim3 gF (FF/128,   BSZ/128);

    // launches 1-5
    wsplit<<<dim3(DD/32, DD/32), tb>>>(Wq, pbf+OF_WQH, pbf+OF_WQL, DD, DD);
    wsplit<<<dim3(DD/32, DD/32), tb>>>(Wk, pbf+OF_WKH, pbf+OF_WKL, DD, DD);
    wsplit<<<dim3(DD/32, DD/32), tb>>>(Wv, pbf+OF_WVH, pbf+OF_WVL, DD, DD);
    wsplit<<<dim3(DD/32, DD/32), tb>>>(Wg, pbf+OF_WGH, pbf+OF_WGL, DD, DD);
    asplit<<<BSZ*DD/1024, 256>>>(x, pbf+OF_XH, pbf+OF_XL);
    // launch 6 (ncu -s 5 catches this): q GEMM
    gemm_bf<0,0><<<gD, blk, GSMEM>>>(pbf+OF_XH, pbf+OF_XL, pbf+OF_WQH, pbf+OF_WQL,
                                     pq, nullptr, nullptr, BSZ, DD, DD, nullptr, nullptr);
    wsplit<<<dim3(2*DD/32, DD/32), tb>>>(Wa, pbf+OF_WAH, pbf+OF_WAL, DD, 2*DD);
    wsplit<<<dim3(DD/32, DD/32), tb>>>(Wo, pbf+OF_WOH, pbf+OF_WOL, DD, DD);
    wsplit<<<dim3(FF/32, DD/32), tb>>>(W1, pbf+OF_W1H, pbf+OF_W1L, DD, FF);
    wsplit<<<dim3(DD/32, FF/32), tb>>>(W2, pbf+OF_W2H, pbf+OF_W2L, FF, DD);

    gemm_bf<0,0><<<gD, blk, GSMEM>>>(pbf+OF_XH, pbf+OF_XL, pbf+OF_WKH, pbf+OF_WKL,
                                     pkv, nullptr, nullptr, BSZ, DD, DD, nullptr, nullptr);
    gemm_bf<0,0><<<gD, blk, GSMEM>>>(pbf+OF_XH, pbf+OF_XL, pbf+OF_WVH, pbf+OF_WVL,
                                     pv, nullptr, nullptr, BSZ, DD, DD, nullptr, nullptr);
    gemm_bf<0,0><<<gD, blk, GSMEM>>>(pbf+OF_XH, pbf+OF_XL, pbf+OF_WGH, pbf+OF_WGL,
                                     pg, nullptr, nullptr, BSZ, DD, DD, nullptr, nullptr);
    gemm_bf<0,0><<<gA, blk, GSMEM>>>(pbf+OF_XH, pbf+OF_XL, pbf+OF_WAH, pbf+OF_WAL,
                                     pa, nullptr, nullptr, BSZ, 2*DD, DD, nullptr, nullptr);

    prep_kernel<<<BSZ*DD/256, 256>>>();
    scan1<<<BB*DD*NC/256, 256>>>();
    scan2<<<(BB*DD+255)/256, 256>>>();
    scan3<<<BB*DD*NC/256, 256>>>();
    gnstats<<<BB*GG, 256>>>();
    gapply<<<BSZ*DD/512, 256>>>(gn_scale, gn_bias);

    gemm_bf<0,0><<<gD, blk, GSMEM>>>(pbf+OF_ZH, pbf+OF_ZL, pbf+OF_WOH, pbf+OF_WOL,
                                     pt1, nullptr, nullptr, BSZ, DD, DD, nullptr, nullptr);
    ln_kernel<1><<<BSZ, 256>>>(x, pt1, px1, pbf+OF_X1H, pbf+OF_X1L, ln1_scale, ln1_bias);

    gemm_bf<1,1><<<gF, blk, GSMEM>>>(pbf+OF_X1H, pbf+OF_X1L, pbf+OF_W1H, pbf+OF_W1L,
                                     nullptr, pbf+OF_HH, pbf+OF_HL, BSZ, FF, DD, b1, nullptr);
    gemm_bf<0,0><<<gD, blk, GSMEM>>>(pbf+OF_HH, pbf+OF_HL, pbf+OF_W2H, pbf+OF_W2L,
                                     pt1, nullptr, nullptr, BSZ, DD, FF, b2, px1);

    ln_kernel<0><<<BSZ, 256>>>(pt1, nullptr, out, nullptr, nullptr, ln2_scale, ln2_bias);
}